// round 3
// baseline (speedup 1.0000x reference)
#include <cuda_runtime.h>
#include <math.h>

#define DIM     512
#define NTOK    256
#define HEADS   8
#define DFF     1365
#define DFF2    2730
#define DFFP    1376        // DFF padded to multiple of 16
#define MAXM    42
#define ROWS    3072        // NBLK*NB*NTOK
#define RMS_EPS 1.1920929e-07f

// ---------------- scratch (device globals; no runtime allocation) ----------------
static __device__ float g_T   [ROWS * DIM];
static __device__ float g_XN  [ROWS * DIM];
static __device__ float g_Q   [ROWS * DIM];
static __device__ float g_KV  [ROWS * 1024];
static __device__ float g_O   [ROWS * DIM];
static __device__ float g_H   [ROWS * DFF2];
static __device__ float g_ACT [ROWS * DFFP];
static __device__ float g_Or  [ROWS * DIM];
static __device__ float g_msg [(size_t)MAXM * 512 * DIM];    // row = (m*2+b)*256+n
static __device__ float g_kvm [(size_t)MAXM * 512 * 1024];   // same row layout, 1024 cols
static __device__ float g_Wvp [DIM * DFFP];                  // padded ff_values_w

// ---------------- packed f32x2 helpers (sm_103a FFMA2 path) ----------------
__device__ __forceinline__ void ffma2(unsigned long long& d,
                                      unsigned long long a,
                                      unsigned long long b) {
    asm("fma.rn.f32x2 %0, %1, %2, %0;" : "+l"(d) : "l"(a), "l"(b));
}
__device__ __forceinline__ unsigned long long fma2_3(unsigned long long a,
                                                     unsigned long long b,
                                                     unsigned long long c) {
    unsigned long long d;
    asm("fma.rn.f32x2 %0, %1, %2, %3;" : "=l"(d) : "l"(a), "l"(b), "l"(c));
    return d;
}
__device__ __forceinline__ unsigned long long mul2(unsigned long long a,
                                                   unsigned long long b) {
    unsigned long long d;
    asm("mul.rn.f32x2 %0, %1, %2;" : "=l"(d) : "l"(a), "l"(b));
    return d;
}
__device__ __forceinline__ unsigned long long dup2(float x) {
    unsigned long long r;
    asm("mov.b64 %0, {%1, %1};" : "=l"(r) : "f"(x));
    return r;
}
__device__ __forceinline__ unsigned long long pk2(float x, float y) {
    unsigned long long r;
    asm("mov.b64 %0, {%1, %2};" : "=l"(r) : "f"(x), "f"(y));
    return r;
}
__device__ __forceinline__ float2 unpack2(unsigned long long v) {
    float2 f;
    asm("mov.b64 {%0, %1}, %2;" : "=f"(f.x), "=f"(f.y) : "l"(v));
    return f;
}

// ---------------- SGEMM:  Y[m,n] = sum_k X[m,k]*W[n,k] (+bias[n]) ----------------
// BM=64, BN=64, BK=16, 256 threads, thread = 4x4 (FFMA2-packed along m).
// Double-buffered smem. Requirements: M%64==0, K%16==0, lda%4==0, W stride==K.
__global__ __launch_bounds__(256, 4) void sgemm_nt(
    const float* __restrict__ X, int lda,
    const float* __restrict__ W,
    const float* __restrict__ bias,
    float* __restrict__ Y,
    int M, int N, int K)
{
    __shared__ __align__(16) float As[2][16][68];
    __shared__ __align__(16) float Bs[2][16][68];

    const int tid  = threadIdx.x;
    const int bm0  = blockIdx.y * 64;
    const int bn0  = blockIdx.x * 64;
    const int m0   = (tid >> 4) * 4;    // 0..60
    const int n0   = (tid & 15) * 4;    // 0..60
    const int lr   = tid >> 2;          // 0..63 loader row
    const int lc4  = (tid & 3) * 4;     // 0,4,8,12 loader k

    unsigned long long acc[2][4];
#pragma unroll
    for (int i = 0; i < 2; i++)
#pragma unroll
        for (int j = 0; j < 4; j++) acc[i][j] = 0ull;

    const float* Xp = X + (size_t)(bm0 + lr) * lda + lc4;
    const float* Wp = W + (size_t)(bn0 + lr) * K + lc4;
    const bool   wok = (bn0 + lr) < N;

    float4 xv, wv;
    xv = *reinterpret_cast<const float4*>(Xp);
    wv = wok ? *reinterpret_cast<const float4*>(Wp) : make_float4(0.f, 0.f, 0.f, 0.f);
    As[0][lc4 + 0][lr] = xv.x; As[0][lc4 + 1][lr] = xv.y;
    As[0][lc4 + 2][lr] = xv.z; As[0][lc4 + 3][lr] = xv.w;
    Bs[0][lc4 + 0][lr] = wv.x; Bs[0][lc4 + 1][lr] = wv.y;
    Bs[0][lc4 + 2][lr] = wv.z; Bs[0][lc4 + 3][lr] = wv.w;
    __syncthreads();

    const int nk = K >> 4;
    for (int t = 0; t < nk; t++) {
        const int buf = t & 1;
        if (t + 1 < nk) {
            const int ko = (t + 1) * 16;
            xv = *reinterpret_cast<const float4*>(Xp + ko);
            wv = wok ? *reinterpret_cast<const float4*>(Wp + ko)
                     : make_float4(0.f, 0.f, 0.f, 0.f);
        }
#pragma unroll
        for (int k = 0; k < 16; k++) {
            ulonglong2 a2 = *reinterpret_cast<const ulonglong2*>(&As[buf][k][m0]);
            float4 b4 = *reinterpret_cast<const float4*>(&Bs[buf][k][n0]);
            unsigned long long b0 = dup2(b4.x), b1 = dup2(b4.y),
                               b2 = dup2(b4.z), b3 = dup2(b4.w);
            ffma2(acc[0][0], a2.x, b0); ffma2(acc[0][1], a2.x, b1);
            ffma2(acc[0][2], a2.x, b2); ffma2(acc[0][3], a2.x, b3);
            ffma2(acc[1][0], a2.y, b0); ffma2(acc[1][1], a2.y, b1);
            ffma2(acc[1][2], a2.y, b2); ffma2(acc[1][3], a2.y, b3);
        }
        if (t + 1 < nk) {
            const int nb = buf ^ 1;
            As[nb][lc4 + 0][lr] = xv.x; As[nb][lc4 + 1][lr] = xv.y;
            As[nb][lc4 + 2][lr] = xv.z; As[nb][lc4 + 3][lr] = xv.w;
            Bs[nb][lc4 + 0][lr] = wv.x; Bs[nb][lc4 + 1][lr] = wv.y;
            Bs[nb][lc4 + 2][lr] = wv.z; Bs[nb][lc4 + 3][lr] = wv.w;
        }
        __syncthreads();
    }

#pragma unroll
    for (int i2 = 0; i2 < 2; i2++) {
        const int m = bm0 + m0 + i2 * 2;
#pragma unroll
        for (int j = 0; j < 4; j++) {
            const int n = bn0 + n0 + j;
            if (n < N) {
                float2 v = unpack2(acc[i2][j]);
                float bb = bias ? bias[n] : 0.f;
                Y[(size_t)m * N + n]       = v.x + bb;
                Y[(size_t)(m + 1) * N + n] = v.y + bb;
            }
        }
    }
}

// ---------------- RMSNorm: one warp per 512-wide row ----------------
__global__ __launch_bounds__(256) void rmsnorm_kernel(
    const float* __restrict__ X, const float* __restrict__ w,
    float* __restrict__ Y, int rows)
{
    int row  = blockIdx.x * 8 + (threadIdx.x >> 5);
    int lane = threadIdx.x & 31;
    if (row >= rows) return;
    const float* xp = X + (size_t)row * DIM;
    float x[16];
    float ss = 0.f;
#pragma unroll
    for (int t = 0; t < 16; t++) {
        x[t] = xp[lane + t * 32];
        ss += x[t] * x[t];
    }
#pragma unroll
    for (int o = 16; o > 0; o >>= 1) ss += __shfl_xor_sync(0xffffffffu, ss, o);
    float rs = rsqrtf(ss * (1.0f / 512.0f) + RMS_EPS);
    float* yp = Y + (size_t)row * DIM;
#pragma unroll
    for (int t = 0; t < 16; t++)
        yp[lane + t * 32] = x[t] * rs * w[lane + t * 32];
}

// ---------------- Self attention (n=256, online softmax, NO scale) ----------------
// grid: (HEADS, 12 batches), block 256 threads = one thread per query row.
__global__ __launch_bounds__(256) void self_attn_kernel(
    const float* __restrict__ Q, const float* __restrict__ KV,
    float* __restrict__ O)
{
    const int h     = blockIdx.x;
    const int batch = blockIdx.y;
    const int i     = threadIdx.x;

    __shared__ __align__(16) float Ks[64][64];
    __shared__ __align__(16) float Vs[64][64];

    unsigned long long qp[32];
    {
        const float4* qq = reinterpret_cast<const float4*>(
            Q + ((size_t)(batch * 256 + i)) * 512 + h * 64);
#pragma unroll
        for (int t = 0; t < 16; t++) {
            float4 v = qq[t];
            qp[2 * t]     = pk2(v.x, v.y);
            qp[2 * t + 1] = pk2(v.z, v.w);
        }
    }

    float m = -1e30f, l = 0.f;
    unsigned long long acc[32];
#pragma unroll
    for (int t = 0; t < 32; t++) acc[t] = 0ull;

    for (int j0 = 0; j0 < 256; j0 += 64) {
        __syncthreads();
#pragma unroll
        for (int s = 0; s < 4; s++) {
            int u  = threadIdx.x + s * 256;
            int jr = u >> 4;
            int c4 = u & 15;
            const float* kp = KV + ((size_t)(batch * 256 + j0 + jr)) * 1024 + h * 64 + c4 * 4;
            *reinterpret_cast<float4*>(&Ks[jr][c4 * 4]) = *reinterpret_cast<const float4*>(kp);
            *reinterpret_cast<float4*>(&Vs[jr][c4 * 4]) = *reinterpret_cast<const float4*>(kp + 512);
        }
        __syncthreads();

        for (int j = 0; j < 64; j++) {
            const ulonglong2* kr = reinterpret_cast<const ulonglong2*>(Ks[j]);
            unsigned long long s0 = 0ull, s1 = 0ull;
#pragma unroll
            for (int t = 0; t < 8; t++) {
                ulonglong2 k0 = kr[2 * t];
                ulonglong2 k1 = kr[2 * t + 1];
                ffma2(s0, qp[4 * t + 0], k0.x);
                ffma2(s1, qp[4 * t + 1], k0.y);
                ffma2(s0, qp[4 * t + 2], k1.x);
                ffma2(s1, qp[4 * t + 3], k1.y);
            }
            float2 sa = unpack2(s0), sb = unpack2(s1);
            float s = (sa.x + sa.y) + (sb.x + sb.y);

            float mn = fmaxf(m, s);
            float f  = __expf(m - mn);
            float p  = __expf(s - mn);
            l = l * f + p;
            unsigned long long fd = dup2(f), pd = dup2(p);
            const ulonglong2* vr = reinterpret_cast<const ulonglong2*>(Vs[j]);
#pragma unroll
            for (int t = 0; t < 16; t++) {
                ulonglong2 vv = vr[t];
                acc[2 * t]     = fma2_3(acc[2 * t],     fd, mul2(vv.x, pd));
                acc[2 * t + 1] = fma2_3(acc[2 * t + 1], fd, mul2(vv.y, pd));
            }
            m = mn;
        }
    }

    float inv = 1.0f / l;
    float* op = O + ((size_t)(batch * 256 + i)) * 512 + h * 64;
#pragma unroll
    for (int t = 0; t < 16; t++) {
        float2 a = unpack2(acc[2 * t]);
        float2 b = unpack2(acc[2 * t + 1]);
        float4 v;
        v.x = a.x * inv; v.y = a.y * inv;
        v.z = b.x * inv; v.w = b.y * inv;
        *reinterpret_cast<float4*>(op + t * 4) = v;
    }
}

// ---------------- Residual attention: one block per query (3072), warp = head ----
__global__ __launch_bounds__(256) void res_attn_kernel(
    const float* __restrict__ Qr, const float* __restrict__ KVM,
    float* __restrict__ Or, int M)
{
    const int r     = blockIdx.x;         // (block*2+b)*256+n
    const int block = r >> 9;
    const int bq    = (r >> 8) & 1;
    const int n     = r & 255;
    const int c     = 2 * block + bq;
    const int bprime = c / 6;             // einops (b blocks) vs (blocks b) quirk

    const int tid  = threadIdx.x;
    const int h    = tid >> 5;
    const int lane = tid & 31;

    __shared__ float qs[512];
    __shared__ float sim[8][64];

    qs[tid]       = Qr[(size_t)r * 512 + tid];
    qs[tid + 256] = Qr[(size_t)r * 512 + tid + 256];
    __syncthreads();

    // scores for this head
    for (int mi = lane; mi < M; mi += 32) {
        const float4* k4 = reinterpret_cast<const float4*>(
            KVM + ((size_t)((mi * 2 + bprime) * 256 + n)) * 1024 + h * 64);
        const float4* q4 = reinterpret_cast<const float4*>(&qs[h * 64]);
        float s = 0.f;
#pragma unroll
        for (int t = 0; t < 16; t++) {
            float4 kk = k4[t];
            float4 qq = q4[t];
            s += qq.x * kk.x + qq.y * kk.y + qq.z * kk.z + qq.w * kk.w;
        }
        sim[h][mi] = s;
    }
    __syncwarp();

    // softmax over m (M <= 42)
    float v0 = (lane < M)      ? sim[h][lane]      : -1e30f;
    float v1 = (lane + 32 < M) ? sim[h][lane + 32] : -1e30f;
    float mx = fmaxf(v0, v1);
#pragma unroll
    for (int o = 16; o > 0; o >>= 1) mx = fmaxf(mx, __shfl_xor_sync(0xffffffffu, mx, o));
    float p0 = (lane < M)      ? __expf(v0 - mx) : 0.f;
    float p1 = (lane + 32 < M) ? __expf(v1 - mx) : 0.f;
    if (lane < M)      sim[h][lane]      = p0;
    if (lane + 32 < M) sim[h][lane + 32] = p1;
    float ls = p0 + p1;
#pragma unroll
    for (int o = 16; o > 0; o >>= 1) ls += __shfl_xor_sync(0xffffffffu, ls, o);
    __syncwarp();

    // out: each lane covers dh = lane, lane+32
    float o0 = 0.f, o1 = 0.f;
    for (int mi = 0; mi < M; mi++) {
        float a = sim[h][mi];
        const float* vp = KVM + ((size_t)((mi * 2 + bprime) * 256 + n)) * 1024 + 512 + h * 64;
        o0 += a * vp[lane];
        o1 += a * vp[lane + 32];
    }
    float inv = 1.0f / ls;
    Or[(size_t)r * 512 + h * 64 + lane]      = o0 * inv;
    Or[(size_t)r * 512 + h * 64 + lane + 32] = o1 * inv;
}

// ---------------- GEGLU (exact erf gelu), writes zero-padded ACT --------------
__global__ void geglu_kernel(const float* __restrict__ H, float* __restrict__ A)
{
    int idx = blockIdx.x * blockDim.x + threadIdx.x;
    if (idx >= ROWS * DFFP) return;
    int row = idx / DFFP;
    int e   = idx - row * DFFP;
    float out = 0.f;
    if (e < DFF) {
        float s = H[(size_t)row * DFF2 + e];
        float g = H[(size_t)row * DFF2 + DFF + e];
        out = s * (0.5f * g * (1.0f + erff(g * 0.70710678118654752440f)));
    }
    A[idx] = out;
}

// ---------------- init: broadcast tokens into T and msg[0..5] -----------------
__global__ void init_bcast_kernel(const float* __restrict__ tokens,
                                  float* __restrict__ T, float* __restrict__ msg)
{
    int idx = blockIdx.x * blockDim.x + threadIdx.x;
    if (idx >= ROWS * DIM) return;
    int dd = idx & 511;
    int rr = idx >> 9;            // (block*2+b)*256+n
    int n  = rr & 255;
    int b  = (rr >> 8) & 1;
    float v = tokens[((size_t)(b * 256 + n)) * 512 + dd];
    T[idx]   = v;
    msg[idx] = v;
}

// ---------------- pad ff_values_w [512,1365] -> [512,1376] --------------------
__global__ void pad_w_kernel(const float* __restrict__ W, float* __restrict__ Wp)
{
    int idx = blockIdx.x * blockDim.x + threadIdx.x;
    if (idx >= DIM * DFFP) return;
    int row = idx / DFFP;
    int col = idx - row * DFFP;
    Wp[idx] = (col < DFF) ? W[(size_t)row * DFF + col] : 0.f;
}

// -------------------------------- launch --------------------------------------
extern "C" void kernel_launch(void* const* d_in, const int* in_sizes, int n_in,
                              void* d_out, int out_size)
{
    const float* tokens      = (const float*)d_in[0];
    const float* attn_norm_w = (const float*)d_in[1];
    const float* attn_wq     = (const float*)d_in[2];
    const float* attn_wkv    = (const float*)d_in[3];
    const float* attn_wo     = (const float*)d_in[4];
    const float* ff_norm_w   = (const float*)d_in[5];
    const float* ff_keys_w   = (const float*)d_in[6];
    const float* ff_keys_b   = (const float*)d_in[7];
    const float* ff_values_w = (const float*)d_in[8];
    const float* ff_values_b = (const float*)d_in[9];
    const float* res_norm_w  = (const float*)d_in[10];
    const float* res_wq      = (const float*)d_in[11];
    const float* res_wkv     = (const float*)d_in[12];
    const float* res_wo      = (const float*)d_in[13];
    float* out = (float*)d_out;

    float *T, *XN, *Q, *KV, *O, *H, *ACT, *Or, *msg, *kvm, *Wvp;
    cudaGetSymbolAddress((void**)&T,   g_T);
    cudaGetSymbolAddress((void**)&XN,  g_XN);
    cudaGetSymbolAddress((void**)&Q,   g_Q);
    cudaGetSymbolAddress((void**)&KV,  g_KV);
    cudaGetSymbolAddress((void**)&O,   g_O);
    cudaGetSymbolAddress((void**)&H,   g_H);
    cudaGetSymbolAddress((void**)&ACT, g_ACT);
    cudaGetSymbolAddress((void**)&Or,  g_Or);
    cudaGetSymbolAddress((void**)&msg, g_msg);
    cudaGetSymbolAddress((void**)&kvm, g_kvm);
    cudaGetSymbolAddress((void**)&Wvp, g_Wvp);

    init_bcast_kernel<<<(ROWS * DIM + 255) / 256, 256>>>(tokens, T, msg);
    pad_w_kernel<<<(DIM * DFFP + 255) / 256, 256>>>(ff_values_w, Wvp);

    int Mtot = 6;
    for (int e = 0; e < 3; e++) {
        // ---- self attention over the 12 flattened sequences ----
        rmsnorm_kernel<<<ROWS / 8, 256>>>(T, attn_norm_w, XN, ROWS);
        sgemm_nt<<<dim3(8, ROWS / 64), 256>>>(XN, 512, attn_wq,  nullptr, Q,  ROWS, 512, 512);
        sgemm_nt<<<dim3(16, ROWS / 64), 256>>>(T,  512, attn_wkv, nullptr, KV, ROWS, 1024, 512);
        self_attn_kernel<<<dim3(HEADS, 12), 256>>>(Q, KV, O);
        float* att_dst = msg + (size_t)Mtot * 512 * DIM;
        sgemm_nt<<<dim3(8, ROWS / 64), 256>>>(O, 512, attn_wo, nullptr, att_dst, ROWS, 512, 512);

        // ---- feedforward (geglu, exact gelu) ----
        rmsnorm_kernel<<<ROWS / 8, 256>>>(T, ff_norm_w, XN, ROWS);
        sgemm_nt<<<dim3((DFF2 + 63) / 64, ROWS / 64), 256>>>(XN, 512, ff_keys_w, ff_keys_b, H, ROWS, DFF2, 512);
        geglu_kernel<<<(ROWS * DFFP + 255) / 256, 256>>>(H, ACT);
        float* ret_dst = msg + (size_t)(Mtot + 6) * 512 * DIM;
        sgemm_nt<<<dim3(8, ROWS / 64), 256>>>(ACT, DFFP, Wvp, ff_values_b, ret_dst, ROWS, 512, DFFP);

        int Mnew = Mtot + 12;

        // ---- KV projection for NEW message slabs only (cached across exchanges) ----
        int startm = (e == 0) ? 0 : Mtot;       // include the 6 initial token slabs once
        int nrows  = (Mnew - startm) * 512;
        sgemm_nt<<<dim3(16, nrows / 64), 256>>>(
            msg + (size_t)startm * 512 * DIM, 512, res_wkv, nullptr,
            kvm + (size_t)startm * 512 * 1024, nrows, 1024, 512);
        Mtot = Mnew;

        // ---- residual pooled attention (1 query over Mtot messages) ----
        rmsnorm_kernel<<<ROWS / 8, 256>>>(T, res_norm_w, XN, ROWS);
        sgemm_nt<<<dim3(8, ROWS / 64), 256>>>(XN, 512, res_wq, nullptr, Q, ROWS, 512, 512);
        res_attn_kernel<<<ROWS, 256>>>(Q, kvm, Or, Mtot);
        float* tdst = (e == 2) ? out : T;
        sgemm_nt<<<dim3(8, ROWS / 64), 256>>>(Or, 512, res_wo, nullptr, tdst, ROWS, 512, 512);
    }
}

// round 5
// speedup vs baseline: 1.8489x; 1.8489x over previous
#include <cuda_runtime.h>
#include <cuda_bf16.h>
#include <math.h>
#include <stdint.h>

#define DIM     512
#define HEADS   8
#define DFF     1365
#define DFF2    2730
#define DFFP    1408        // DFF padded to multiple of 32 (BK)
#define MAXM    42
#define ROWS    3072
#define RMS_EPS 1.1920929e-07f

// ---------------- scratch (device globals; no runtime allocation) ----------------
static __device__ float g_T   [ROWS * DIM];
static __device__ float g_Q   [ROWS * DIM];
static __device__ float g_KV  [ROWS * 1024];
static __device__ float g_H   [ROWS * DFF2];
static __device__ float g_kvm [(size_t)MAXM * 512 * 1024];

static __device__ __nv_bfloat16 g_Xh[ROWS * DFFP];
static __device__ __nv_bfloat16 g_Xl[ROWS * DFFP];
static __device__ __nv_bfloat16 g_Th[ROWS * DIM];
static __device__ __nv_bfloat16 g_Tl[ROWS * DIM];
static __device__ __nv_bfloat16 g_msgh[(size_t)MAXM * 512 * 512];
static __device__ __nv_bfloat16 g_msgl[(size_t)MAXM * 512 * 512];

// weight arena (bf16 hi/lo)
#define OFF_WQ   0
#define OFF_WKV  262144
#define OFF_WO   786432
#define OFF_FFK  1048576
#define OFF_FFV  2446336
#define OFF_RQ   3167232
#define OFF_RKV  3429376
#define OFF_RWO  3953664
#define WTOTAL   4215808
static __device__ __nv_bfloat16 g_Wh[WTOTAL];
static __device__ __nv_bfloat16 g_Wl[WTOTAL];

// ---------------- small helpers ----------------
__device__ __forceinline__ void split_bf16(float v, __nv_bfloat16& h, __nv_bfloat16& l) {
    h = __float2bfloat16(v);
    l = __float2bfloat16(v - __bfloat162float(h));
}
__device__ __forceinline__ uint32_t smem_u32(const void* p) {
    uint32_t a;
    asm("{ .reg .u64 t; cvta.to.shared.u64 t, %1; cvt.u32.u64 %0, t; }" : "=r"(a) : "l"(p));
    return a;
}
__device__ __forceinline__ void cp16(uint32_t dst, const void* src, uint32_t sz) {
    asm volatile("cp.async.cg.shared.global [%0], [%1], 16, %2;"
                 :: "r"(dst), "l"(src), "r"(sz));
}
__device__ __forceinline__ void ldsm4(uint32_t& r0, uint32_t& r1, uint32_t& r2,
                                      uint32_t& r3, uint32_t addr) {
    asm volatile("ldmatrix.sync.aligned.m8n8.x4.shared.b16 {%0,%1,%2,%3}, [%4];"
                 : "=r"(r0), "=r"(r1), "=r"(r2), "=r"(r3) : "r"(addr));
}
__device__ __forceinline__ void mma16816(float* c, const uint32_t* a, const uint32_t* b) {
    asm volatile(
        "mma.sync.aligned.m16n8k16.row.col.f32.bf16.bf16.f32 "
        "{%0,%1,%2,%3}, {%4,%5,%6,%7}, {%8,%9}, {%0,%1,%2,%3};"
        : "+f"(c[0]), "+f"(c[1]), "+f"(c[2]), "+f"(c[3])
        : "r"(a[0]), "r"(a[1]), "r"(a[2]), "r"(a[3]), "r"(b[0]), "r"(b[1]));
}

// ---------------- tensor-core split-bf16 GEMM ----------------------------------
// Y[m,n] = sum_k X[m,k] * W[n,k] (+bias[n]); X,W given as bf16 hi/lo pairs.
// BM=128, BN=64, BK=32, 256 threads (8 warps, 4x2), warp tile 32x32.
// Requirements: M%128==0, K%32==0, strides (bf16 elems) %8==0.
// smem per buffer: 384 rows x 80B = 30720B; double buffered = 61440B.
#define GSMEM 61440

__device__ __forceinline__ void g_loads(
    uint32_t sb, int tid, int buf, int ck,
    const __nv_bfloat16* Ah, const __nv_bfloat16* Al, int lda,
    const __nv_bfloat16* Bh, const __nv_bfloat16* Bl,
    int K, int N, int bm0, int bn0)
{
    const uint32_t bufbase = sb + (uint32_t)buf * 30720u;
#pragma unroll
    for (int i = 0; i < 6; i++) {
        int c = tid + i * 256;
        int R = c >> 2;            // 0..383
        int q = c & 3;             // 16B chunk within row (32 bf16 = 4 chunks)
        uint32_t dst = bufbase + (uint32_t)R * 80u + (uint32_t)q * 16u;
        const __nv_bfloat16* src;
        uint32_t sz = 16;
        if (R < 256) {
            src = (R < 128 ? Ah : Al) + (size_t)(bm0 + (R & 127)) * lda;
        } else {
            int rg = bn0 + (R & 63);
            if (rg >= N) { rg = 0; sz = 0; }
            src = (R < 320 ? Bh : Bl) + (size_t)rg * K;
        }
        cp16(dst, src + ck * 32 + q * 8, sz);
    }
    asm volatile("cp.async.commit_group;");
}

__global__ __launch_bounds__(256) void gemm_mma(
    const __nv_bfloat16* __restrict__ Ah, const __nv_bfloat16* __restrict__ Al, int lda,
    const __nv_bfloat16* __restrict__ Bh, const __nv_bfloat16* __restrict__ Bl,
    const float* __restrict__ bias,
    float* __restrict__ Yf,
    __nv_bfloat16* __restrict__ Yh, __nv_bfloat16* __restrict__ Yl,
    int M, int N, int K)
{
    extern __shared__ __align__(16) char smem[];
    const uint32_t sb = smem_u32(smem);
    const int tid  = threadIdx.x;
    const int wid  = tid >> 5;
    const int lane = tid & 31;
    const int bn0  = blockIdx.x * 64;
    const int bm0  = blockIdx.y * 128;
    const int m0w  = (wid & 3) * 32;
    const int n0w  = (wid >> 2) * 32;

    float C[2][4][4];
#pragma unroll
    for (int mt = 0; mt < 2; mt++)
#pragma unroll
        for (int nt = 0; nt < 4; nt++)
#pragma unroll
            for (int v = 0; v < 4; v++) C[mt][nt][v] = 0.f;

    // ldmatrix base addresses (byte offsets; add buf*30720 + ks*32 at use)
    uint32_t aoffH[2], aoffL[2], boffH[2], boffL[2];
#pragma unroll
    for (int mt = 0; mt < 2; mt++) {
        uint32_t row = (uint32_t)(m0w + mt * 16 + (lane & 15));
        uint32_t kb  = (uint32_t)((lane >> 4) * 16);
        aoffH[mt] = sb + row * 80u + kb;
        aoffL[mt] = aoffH[mt] + 10240u;          // A_l rows start at 128*80
    }
#pragma unroll
    for (int bt = 0; bt < 2; bt++) {
        uint32_t row = (uint32_t)(n0w + bt * 16 + (lane & 7) + ((lane >> 4) << 3));
        uint32_t kb  = (uint32_t)(((lane >> 3) & 1) * 16);
        boffH[bt] = sb + 20480u + row * 80u + kb; // B_h rows start at 256*80
        boffL[bt] = boffH[bt] + 5120u;            // B_l rows start at 320*80
    }

    const int nk = K >> 5;
    g_loads(sb, tid, 0, 0, Ah, Al, lda, Bh, Bl, K, N, bm0, bn0);

    for (int t = 0; t < nk; t++) {
        const int buf = t & 1;
        if (t + 1 < nk) {
            g_loads(sb, tid, buf ^ 1, t + 1, Ah, Al, lda, Bh, Bl, K, N, bm0, bn0);
            asm volatile("cp.async.wait_group 1;" ::: "memory");
        } else {
            asm volatile("cp.async.wait_group 0;" ::: "memory");
        }
        __syncthreads();

        const uint32_t bofs = (uint32_t)buf * 30720u;
#pragma unroll
        for (int ks = 0; ks < 2; ks++) {
            const uint32_t ko = bofs + (uint32_t)ks * 32u;
            uint32_t ah[2][4], al[2][4], bh[4][2], bl[4][2];
#pragma unroll
            for (int mt = 0; mt < 2; mt++) {
                ldsm4(ah[mt][0], ah[mt][1], ah[mt][2], ah[mt][3], aoffH[mt] + ko);
                ldsm4(al[mt][0], al[mt][1], al[mt][2], al[mt][3], aoffL[mt] + ko);
            }
            ldsm4(bh[0][0], bh[0][1], bh[1][0], bh[1][1], boffH[0] + ko);
            ldsm4(bh[2][0], bh[2][1], bh[3][0], bh[3][1], boffH[1] + ko);
            ldsm4(bl[0][0], bl[0][1], bl[1][0], bl[1][1], boffL[0] + ko);
            ldsm4(bl[2][0], bl[2][1], bl[3][0], bl[3][1], boffL[1] + ko);
#pragma unroll
            for (int mt = 0; mt < 2; mt++)
#pragma unroll
                for (int nt = 0; nt < 4; nt++) {
                    mma16816(C[mt][nt], ah[mt], bh[nt]);
                    mma16816(C[mt][nt], ah[mt], bl[nt]);
                    mma16816(C[mt][nt], al[mt], bh[nt]);
                }
        }
        __syncthreads();
    }

    // epilogue: c0,c1 -> (row, col..col+1); c2,c3 -> (row+8, col..col+1)
#pragma unroll
    for (int mt = 0; mt < 2; mt++) {
        const int row = bm0 + m0w + mt * 16 + (lane >> 2);
#pragma unroll
        for (int nt = 0; nt < 4; nt++) {
            const int col = bn0 + n0w + nt * 8 + (lane & 3) * 2;
            if (col < N) {
                float b0 = bias ? bias[col]     : 0.f;
                float b1 = bias ? bias[col + 1] : 0.f;
                float v00 = C[mt][nt][0] + b0, v01 = C[mt][nt][1] + b1;
                float v10 = C[mt][nt][2] + b0, v11 = C[mt][nt][3] + b1;
                const size_t o0 = (size_t)row * N + col;
                const size_t o1 = (size_t)(row + 8) * N + col;
                if (Yf) {
                    *reinterpret_cast<float2*>(Yf + o0) = make_float2(v00, v01);
                    *reinterpret_cast<float2*>(Yf + o1) = make_float2(v10, v11);
                }
                if (Yh) {
                    __nv_bfloat16 h0, l0, h1, l1;
                    split_bf16(v00, h0, l0); split_bf16(v01, h1, l1);
                    *reinterpret_cast<__nv_bfloat162*>(Yh + o0) = __nv_bfloat162(h0, h1);
                    *reinterpret_cast<__nv_bfloat162*>(Yl + o0) = __nv_bfloat162(l0, l1);
                    split_bf16(v10, h0, l0); split_bf16(v11, h1, l1);
                    *reinterpret_cast<__nv_bfloat162*>(Yh + o1) = __nv_bfloat162(h0, h1);
                    *reinterpret_cast<__nv_bfloat162*>(Yl + o1) = __nv_bfloat162(l0, l1);
                }
            }
        }
    }
}

// ---------------- packed f32x2 helpers for SIMT attention ----------------
__device__ __forceinline__ void ffma2(unsigned long long& d, unsigned long long a,
                                      unsigned long long b) {
    asm("fma.rn.f32x2 %0, %1, %2, %0;" : "+l"(d) : "l"(a), "l"(b));
}
__device__ __forceinline__ unsigned long long fma2_3(unsigned long long a,
                                                     unsigned long long b,
                                                     unsigned long long c) {
    unsigned long long d;
    asm("fma.rn.f32x2 %0, %1, %2, %3;" : "=l"(d) : "l"(a), "l"(b), "l"(c));
    return d;
}
__device__ __forceinline__ unsigned long long mul2(unsigned long long a,
                                                   unsigned long long b) {
    unsigned long long d;
    asm("mul.rn.f32x2 %0, %1, %2;" : "=l"(d) : "l"(a), "l"(b));
    return d;
}
__device__ __forceinline__ unsigned long long dup2(float x) {
    unsigned long long r;
    asm("mov.b64 %0, {%1, %1};" : "=l"(r) : "f"(x));
    return r;
}
__device__ __forceinline__ unsigned long long pk2(float x, float y) {
    unsigned long long r;
    asm("mov.b64 %0, {%1, %2};" : "=l"(r) : "f"(x), "f"(y));
    return r;
}
__device__ __forceinline__ float2 unpack2(unsigned long long v) {
    float2 f;
    asm("mov.b64 {%0, %1}, %2;" : "=f"(f.x), "=f"(f.y) : "l"(v));
    return f;
}

// ---------------- RMSNorm -> split bf16 (stride 512) ----------------
__global__ __launch_bounds__(256) void rmsnorm_split(
    const float* __restrict__ X, const float* __restrict__ w,
    __nv_bfloat16* __restrict__ Yh, __nv_bfloat16* __restrict__ Yl, int rows)
{
    int row  = blockIdx.x * 8 + (threadIdx.x >> 5);
    int lane = threadIdx.x & 31;
    if (row >= rows) return;
    const float* xp = X + (size_t)row * DIM;
    float x[16];
    float ss = 0.f;
#pragma unroll
    for (int t = 0; t < 16; t++) { x[t] = xp[lane + t * 32]; ss += x[t] * x[t]; }
#pragma unroll
    for (int o = 16; o > 0; o >>= 1) ss += __shfl_xor_sync(0xffffffffu, ss, o);
    float rs = rsqrtf(ss * (1.0f / 512.0f) + RMS_EPS);
#pragma unroll
    for (int t = 0; t < 16; t++) {
        int c = lane + t * 32;
        float y = x[t] * rs * w[c];
        __nv_bfloat16 h, l;
        split_bf16(y, h, l);
        Yh[(size_t)row * DIM + c] = h;
        Yl[(size_t)row * DIM + c] = l;
    }
}

// ---------------- Self attention (online softmax, NO scale), split output ------
__global__ __launch_bounds__(256) void self_attn_kernel(
    const float* __restrict__ Q, const float* __restrict__ KV,
    __nv_bfloat16* __restrict__ Oh, __nv_bfloat16* __restrict__ Ol)
{
    const int h     = blockIdx.x;
    const int batch = blockIdx.y;
    const int i     = threadIdx.x;

    __shared__ __align__(16) float Ks[64][64];
    __shared__ __align__(16) float Vs[64][64];

    unsigned long long qp[32];
    {
        const float4* qq = reinterpret_cast<const float4*>(
            Q + ((size_t)(batch * 256 + i)) * 512 + h * 64);
#pragma unroll
        for (int t = 0; t < 16; t++) {
            float4 v = qq[t];
            qp[2 * t]     = pk2(v.x, v.y);
            qp[2 * t + 1] = pk2(v.z, v.w);
        }
    }

    float m = -1e30f, l = 0.f;
    unsigned long long acc[32];
#pragma unroll
    for (int t = 0; t < 32; t++) acc[t] = 0ull;

    for (int j0 = 0; j0 < 256; j0 += 64) {
        __syncthreads();
#pragma unroll
        for (int s = 0; s < 4; s++) {
            int u  = threadIdx.x + s * 256;
            int jr = u >> 4;
            int c4 = u & 15;
            const float* kp = KV + ((size_t)(batch * 256 + j0 + jr)) * 1024 + h * 64 + c4 * 4;
            *reinterpret_cast<float4*>(&Ks[jr][c4 * 4]) = *reinterpret_cast<const float4*>(kp);
            *reinterpret_cast<float4*>(&Vs[jr][c4 * 4]) = *reinterpret_cast<const float4*>(kp + 512);
        }
        __syncthreads();

        for (int j = 0; j < 64; j++) {
            const ulonglong2* kr = reinterpret_cast<const ulonglong2*>(Ks[j]);
            unsigned long long s0 = 0ull, s1 = 0ull;
#pragma unroll
            for (int t = 0; t < 8; t++) {
                ulonglong2 k0 = kr[2 * t];
                ulonglong2 k1 = kr[2 * t + 1];
                ffma2(s0, qp[4 * t + 0], k0.x);
                ffma2(s1, qp[4 * t + 1], k0.y);
                ffma2(s0, qp[4 * t + 2], k1.x);
                ffma2(s1, qp[4 * t + 3], k1.y);
            }
            float2 sa = unpack2(s0), sb = unpack2(s1);
            float s = (sa.x + sa.y) + (sb.x + sb.y);

            float mn = fmaxf(m, s);
            float f  = __expf(m - mn);
            float p  = __expf(s - mn);
            l = l * f + p;
            unsigned long long fd = dup2(f), pd = dup2(p);
            const ulonglong2* vr = reinterpret_cast<const ulonglong2*>(Vs[j]);
#pragma unroll
            for (int t = 0; t < 16; t++) {
                ulonglong2 vv = vr[t];
                acc[2 * t]     = fma2_3(acc[2 * t],     fd, mul2(vv.x, pd));
                acc[2 * t + 1] = fma2_3(acc[2 * t + 1], fd, mul2(vv.y, pd));
            }
            m = mn;
        }
    }

    float inv = 1.0f / l;
    size_t ob = ((size_t)(batch * 256 + i)) * 512 + h * 64;
#pragma unroll
    for (int t = 0; t < 32; t++) {
        float2 a = unpack2(acc[t]);
        __nv_bfloat16 hh, ll;
        split_bf16(a.x * inv, hh, ll);
        Oh[ob + 2 * t]     = hh; Ol[ob + 2 * t]     = ll;
        split_bf16(a.y * inv, hh, ll);
        Oh[ob + 2 * t + 1] = hh; Ol[ob + 2 * t + 1] = ll;
    }
}

// ---------------- Residual attention, split output ----------------
__global__ __launch_bounds__(256) void res_attn_kernel(
    const float* __restrict__ Qr, const float* __restrict__ KVM,
    __nv_bfloat16* __restrict__ Oh, __nv_bfloat16* __restrict__ Ol, int M)
{
    const int r      = blockIdx.x;
    const int block  = r >> 9;
    const int bq     = (r >> 8) & 1;
    const int n      = r & 255;
    const int c      = 2 * block + bq;
    const int bprime = c / 6;

    const int tid  = threadIdx.x;
    const int h    = tid >> 5;
    const int lane = tid & 31;

    __shared__ float qs[512];
    __shared__ float sim[8][64];

    qs[tid]       = Qr[(size_t)r * 512 + tid];
    qs[tid + 256] = Qr[(size_t)r * 512 + tid + 256];
    __syncthreads();

    for (int mi = lane; mi < M; mi += 32) {
        const float4* k4 = reinterpret_cast<const float4*>(
            KVM + ((size_t)((mi * 2 + bprime) * 256 + n)) * 1024 + h * 64);
        const float4* q4 = reinterpret_cast<const float4*>(&qs[h * 64]);
        float s = 0.f;
#pragma unroll
        for (int t = 0; t < 16; t++) {
            float4 kk = k4[t];
            float4 qq = q4[t];
            s += qq.x * kk.x + qq.y * kk.y + qq.z * kk.z + qq.w * kk.w;
        }
        sim[h][mi] = s;
    }
    __syncwarp();

    float v0 = (lane < M)      ? sim[h][lane]      : -1e30f;
    float v1 = (lane + 32 < M) ? sim[h][lane + 32] : -1e30f;
    float mx = fmaxf(v0, v1);
#pragma unroll
    for (int o = 16; o > 0; o >>= 1) mx = fmaxf(mx, __shfl_xor_sync(0xffffffffu, mx, o));
    float p0 = (lane < M)      ? __expf(v0 - mx) : 0.f;
    float p1 = (lane + 32 < M) ? __expf(v1 - mx) : 0.f;
    if (lane < M)      sim[h][lane]      = p0;
    if (lane + 32 < M) sim[h][lane + 32] = p1;
    float ls = p0 + p1;
#pragma unroll
    for (int o = 16; o > 0; o >>= 1) ls += __shfl_xor_sync(0xffffffffu, ls, o);
    __syncwarp();

    float o0 = 0.f, o1 = 0.f;
    for (int mi = 0; mi < M; mi++) {
        float a = sim[h][mi];
        const float* vp = KVM + ((size_t)((mi * 2 + bprime) * 256 + n)) * 1024 + 512 + h * 64;
        o0 += a * vp[lane];
        o1 += a * vp[lane + 32];
    }
    float inv = 1.0f / ls;
    __nv_bfloat16 hh, ll;
    split_bf16(o0 * inv, hh, ll);
    Oh[(size_t)r * 512 + h * 64 + lane] = hh;
    Ol[(size_t)r * 512 + h * 64 + lane] = ll;
    split_bf16(o1 * inv, hh, ll);
    Oh[(size_t)r * 512 + h * 64 + lane + 32] = hh;
    Ol[(size_t)r * 512 + h * 64 + lane + 32] = ll;
}

// ---------------- GEGLU -> split bf16 (stride DFFP, zero-padded) ----------------
__global__ void geglu_split(const float* __restrict__ H,
                            __nv_bfloat16* __restrict__ Ah,
                            __nv_bfloat16* __restrict__ Al)
{
    int idx = blockIdx.x * blockDim.x + threadIdx.x;
    if (idx >= ROWS * DFFP) return;
    int row = idx / DFFP;
    int e   = idx - row * DFFP;
    float out = 0.f;
    if (e < DFF) {
        float s = H[(size_t)row * DFF2 + e];
        float g = H[(size_t)row * DFF2 + DFF + e];
        out = s * (0.5f * g * (1.0f + erff(g * 0.70710678118654752440f)));
    }
    __nv_bfloat16 h, l;
    split_bf16(out, h, l);
    Ah[idx] = h;
    Al[idx] = l;
}

// ---------------- init: broadcast tokens -> T (fp32+split) + msg[0..5] split ----
__global__ void init_bcast_kernel(const float* __restrict__ tokens,
                                  float* __restrict__ T,
                                  __nv_bfloat16* __restrict__ Th, __nv_bfloat16* __restrict__ Tl,
                                  __nv_bfloat16* __restrict__ Mh, __nv_bfloat16* __restrict__ Ml)
{
    int idx = blockIdx.x * blockDim.x + threadIdx.x;
    if (idx >= ROWS * DIM) return;
    int dd = idx & 511;
    int rr = idx >> 9;
    int n  = rr & 255;
    int b  = (rr >> 8) & 1;
    float v = tokens[((size_t)(b * 256 + n)) * 512 + dd];
    T[idx] = v;
    __nv_bfloat16 h, l;
    split_bf16(v, h, l);
    Th[idx] = h; Tl[idx] = l;
    Mh[idx] = h; Ml[idx] = l;
}

// ---------------- weight conversion ----------------
__global__ void convw_kernel(const float* __restrict__ W,
                             __nv_bfloat16* __restrict__ Wh, __nv_bfloat16* __restrict__ Wl,
                             int count)
{
    int idx = blockIdx.x * blockDim.x + threadIdx.x;
    if (idx >= count) return;
    __nv_bfloat16 h, l;
    split_bf16(W[idx], h, l);
    Wh[idx] = h; Wl[idx] = l;
}

// ff_values_w [512,1365] -> padded [512,1408] split
__global__ void convw_pad_kernel(const float* __restrict__ W,
                                 __nv_bfloat16* __restrict__ Wh, __nv_bfloat16* __restrict__ Wl)
{
    int idx = blockIdx.x * blockDim.x + threadIdx.x;
    if (idx >= DIM * DFFP) return;
    int row = idx / DFFP;
    int col = idx - row * DFFP;
    float v = (col < DFF) ? W[(size_t)row * DFF + col] : 0.f;
    __nv_bfloat16 h, l;
    split_bf16(v, h, l);
    Wh[idx] = h; Wl[idx] = l;
}

// -------------------------------- launch --------------------------------------
static inline void launch_gemm(const __nv_bfloat16* Ah, const __nv_bfloat16* Al, int lda,
                               const __nv_bfloat16* Bh, const __nv_bfloat16* Bl,
                               const float* bias, float* Yf,
                               __nv_bfloat16* Yh, __nv_bfloat16* Yl,
                               int M, int N, int K)
{
    dim3 grid((N + 63) / 64, M / 128);
    gemm_mma<<<grid, 256, GSMEM>>>(Ah, Al, lda, Bh, Bl, bias, Yf, Yh, Yl, M, N, K);
}

extern "C" void kernel_launch(void* const* d_in, const int* in_sizes, int n_in,
                              void* d_out, int out_size)
{
    const float* tokens      = (const float*)d_in[0];
    const float* attn_norm_w = (const float*)d_in[1];
    const float* attn_wq     = (const float*)d_in[2];
    const float* attn_wkv    = (const float*)d_in[3];
    const float* attn_wo     = (const float*)d_in[4];
    const float* ff_norm_w   = (const float*)d_in[5];
    const float* ff_keys_w   = (const float*)d_in[6];
    const float* ff_keys_b   = (const float*)d_in[7];
    const float* ff_values_w = (const float*)d_in[8];
    const float* ff_values_b = (const float*)d_in[9];
    const float* res_norm_w  = (const float*)d_in[10];
    const float* res_wq      = (const float*)d_in[11];
    const float* res_wkv     = (const float*)d_in[12];
    const float* res_wo      = (const float*)d_in[13];
    float* out = (float*)d_out;

    cudaFuncSetAttribute(gemm_mma, cudaFuncAttributeMaxDynamicSharedMemorySize, GSMEM);

    float *T, *Q, *KV, *H, *kvm;
    __nv_bfloat16 *Xh, *Xl, *Th, *Tl, *Mh, *Ml, *Wh, *Wl;
    cudaGetSymbolAddress((void**)&T,   g_T);
    cudaGetSymbolAddress((void**)&Q,   g_Q);
    cudaGetSymbolAddress((void**)&KV,  g_KV);
    cudaGetSymbolAddress((void**)&H,   g_H);
    cudaGetSymbolAddress((void**)&kvm, g_kvm);
    cudaGetSymbolAddress((void**)&Xh,  g_Xh);
    cudaGetSymbolAddress((void**)&Xl,  g_Xl);
    cudaGetSymbolAddress((void**)&Th,  g_Th);
    cudaGetSymbolAddress((void**)&Tl,  g_Tl);
    cudaGetSymbolAddress((void**)&Mh,  g_msgh);
    cudaGetSymbolAddress((void**)&Ml,  g_msgl);
    cudaGetSymbolAddress((void**)&Wh,  g_Wh);
    cudaGetSymbolAddress((void**)&Wl,  g_Wl);

    // weights -> split bf16
    struct { const float* w; int off; int cnt; } ws[] = {
        { attn_wq,   OFF_WQ,  512 * 512  },
        { attn_wkv,  OFF_WKV, 1024 * 512 },
        { attn_wo,   OFF_WO,  512 * 512  },
        { ff_keys_w, OFF_FFK, DFF2 * 512 },
        { res_wq,    OFF_RQ,  512 * 512  },
        { res_wkv,   OFF_RKV, 1024 * 512 },
        { res_wo,    OFF_RWO, 512 * 512  },
    };
    for (auto& e : ws)
        convw_kernel<<<(e.cnt + 255) / 256, 256>>>(e.w, Wh + e.off, Wl + e.off, e.cnt);
    convw_pad_kernel<<<(DIM * DFFP + 255) / 256, 256>>>(ff_values_w, Wh + OFF_FFV, Wl + OFF_FFV);

    init_bcast_kernel<<<(ROWS * DIM + 255) / 256, 256>>>(tokens, T, Th, Tl, Mh, Ml);

    int Mtot = 6;
    for (int e = 0; e < 3; e++) {
        // ---- self attention ----
        rmsnorm_split<<<ROWS / 8, 256>>>(T, attn_norm_w, Xh, Xl, ROWS);
        launch_gemm(Xh, Xl, 512, Wh + OFF_WQ, Wl + OFF_WQ, nullptr,
                    Q, nullptr, nullptr, ROWS, 512, 512);
        launch_gemm(Th, Tl, 512, Wh + OFF_WKV, Wl + OFF_WKV, nullptr,
                    KV, nullptr, nullptr, ROWS, 1024, 512);
        self_attn_kernel<<<dim3(HEADS, 12), 256>>>(Q, KV, Xh, Xl);
        launch_gemm(Xh, Xl, 512, Wh + OFF_WO, Wl + OFF_WO, nullptr,
                    nullptr, Mh + (size_t)Mtot * 512 * 512, Ml + (size_t)Mtot * 512 * 512,
                    ROWS, 512, 512);

        // ---- feedforward ----
        rmsnorm_split<<<ROWS / 8, 256>>>(T, ff_norm_w, Xh, Xl, ROWS);
        launch_gemm(Xh, Xl, 512, Wh + OFF_FFK, Wl + OFF_FFK, ff_keys_b,
                    H, nullptr, nullptr, ROWS, DFF2, 512);
        geglu_split<<<(ROWS * DFFP + 255) / 256, 256>>>(H, Xh, Xl);
        launch_gemm(Xh, Xl, DFFP, Wh + OFF_FFV, Wl + OFF_FFV, ff_values_b,
                    nullptr, Mh + (size_t)(Mtot + 6) * 512 * 512,
                    Ml + (size_t)(Mtot + 6) * 512 * 512, ROWS, 512, DFFP);

        int Mnew = Mtot + 12;

        // ---- KV projection for new message slabs (cached across exchanges) ----
        int startm = (e == 0) ? 0 : Mtot;
        int nrows  = (Mnew - startm) * 512;
        launch_gemm(Mh + (size_t)startm * 512 * 512, Ml + (size_t)startm * 512 * 512, 512,
                    Wh + OFF_RKV, Wl + OFF_RKV, nullptr,
                    kvm + (size_t)startm * 512 * 1024, nullptr, nullptr,
                    nrows, 1024, 512);
        Mtot = Mnew;

        // ---- residual pooled attention ----
        rmsnorm_split<<<ROWS / 8, 256>>>(T, res_norm_w, Xh, Xl, ROWS);
        launch_gemm(Xh, Xl, 512, Wh + OFF_RQ, Wl + OFF_RQ, nullptr,
                    Q, nullptr, nullptr, ROWS, 512, 512);
        res_attn_kernel<<<ROWS, 256>>>(Q, kvm, Xh, Xl, Mtot);
        if (e == 2) {
            launch_gemm(Xh, Xl, 512, Wh + OFF_RWO, Wl + OFF_RWO, nullptr,
                        out, nullptr, nullptr, ROWS, 512, 512);
        } else {
            launch_gemm(Xh, Xl, 512, Wh + OFF_RWO, Wl + OFF_RWO, nullptr,
                        T, Th, Tl, ROWS, 512, 512);
        }
    }
}

// round 6
// speedup vs baseline: 3.5075x; 1.8970x over previous
#include <cuda_runtime.h>
#include <cuda_bf16.h>
#include <math.h>
#include <stdint.h>

#define DIM     512
#define HEADS   8
#define DFF     1365
#define DFF2    2730
#define DFFP    1408            // DFF padded (K multiple of 32)
#define CROWS   1024            // compressed rows: (g,b,n)
#define NBIG    3756            // 512 + 2730 + 512 + 2 align pad
#define QRES_OFF 3242           // 512 + 2730
#define RMS_EPS 1.1920929e-07f

// ---------------- scratch (device globals) ----------------
static __device__ float g_B   [CROWS * NBIG];     // [Q | H | Qres]
static __device__ float g_T   [CROWS * DIM];
static __device__ float g_KV  [CROWS * 1024];
static __device__ float g_kvm [512 * 1024 + 6 * 1024 * 1024]; // tok + (att,ret)x3
static __device__ float g_bias[NBIG];

static __device__ __nv_bfloat16 g_XNh[CROWS * DIM],  g_XNl[CROWS * DIM];
static __device__ __nv_bfloat16 g_XAh[CROWS * DIM],  g_XAl[CROWS * DIM];
static __device__ __nv_bfloat16 g_ACTh[CROWS * DFFP], g_ACTl[CROWS * DFFP];
static __device__ __nv_bfloat16 g_RETh[CROWS * DIM], g_RETl[CROWS * DIM];
static __device__ __nv_bfloat16 g_XRh[CROWS * DIM],  g_XRl[CROWS * DIM];
static __device__ __nv_bfloat16 g_Th [CROWS * DIM],  g_Tl [CROWS * DIM];

static __device__ __nv_bfloat16 g_Wbigh[NBIG * 512], g_Wbigl[NBIG * 512];
static __device__ __nv_bfloat16 g_Wkvh[1024 * 512],  g_Wkvl[1024 * 512];
static __device__ __nv_bfloat16 g_Rkvh[1024 * 512],  g_Rkvl[1024 * 512];
static __device__ __nv_bfloat16 g_WoTh[512 * 512],   g_WoTl[512 * 512];
static __device__ __nv_bfloat16 g_Wvph[512 * DFFP],  g_Wvpl[512 * DFFP];
static __device__ __nv_bfloat16 g_Rwoh[512 * 512],   g_Rwol[512 * 512];
static __device__ __nv_bfloat16 g_Cath[1024 * 512],  g_Catl[1024 * 512];

// ---------------- helpers ----------------
__device__ __forceinline__ void split_bf16(float v, __nv_bfloat16& h, __nv_bfloat16& l) {
    h = __float2bfloat16(v);
    l = __float2bfloat16(v - __bfloat162float(h));
}
__device__ __forceinline__ uint32_t smem_u32(const void* p) {
    uint32_t a;
    asm("{ .reg .u64 t; cvta.to.shared.u64 t, %1; cvt.u32.u64 %0, t; }" : "=r"(a) : "l"(p));
    return a;
}
__device__ __forceinline__ void cp16(uint32_t dst, const void* src, uint32_t sz) {
    asm volatile("cp.async.cg.shared.global [%0], [%1], 16, %2;"
                 :: "r"(dst), "l"(src), "r"(sz));
}
__device__ __forceinline__ void ldsm4(uint32_t& r0, uint32_t& r1, uint32_t& r2,
                                      uint32_t& r3, uint32_t addr) {
    asm volatile("ldmatrix.sync.aligned.m8n8.x4.shared.b16 {%0,%1,%2,%3}, [%4];"
                 : "=r"(r0), "=r"(r1), "=r"(r2), "=r"(r3) : "r"(addr));
}
__device__ __forceinline__ void mma16816(float* c, const uint32_t* a, const uint32_t* b) {
    asm volatile(
        "mma.sync.aligned.m16n8k16.row.col.f32.bf16.bf16.f32 "
        "{%0,%1,%2,%3}, {%4,%5,%6,%7}, {%8,%9}, {%0,%1,%2,%3};"
        : "+f"(c[0]), "+f"(c[1]), "+f"(c[2]), "+f"(c[3])
        : "r"(a[0]), "r"(a[1]), "r"(a[2]), "r"(a[3]), "r"(b[0]), "r"(b[1]));
}

// ---------------- tensor-core split-bf16 GEMM (as R5) --------------------------
#define GSMEM 61440

__device__ __forceinline__ void g_loads(
    uint32_t sb, int tid, int buf, int ck,
    const __nv_bfloat16* Ah, const __nv_bfloat16* Al, int lda,
    const __nv_bfloat16* Bh, const __nv_bfloat16* Bl,
    int K, int N, int bm0, int bn0)
{
    const uint32_t bufbase = sb + (uint32_t)buf * 30720u;
#pragma unroll
    for (int i = 0; i < 6; i++) {
        int c = tid + i * 256;
        int R = c >> 2;
        int q = c & 3;
        uint32_t dst = bufbase + (uint32_t)R * 80u + (uint32_t)q * 16u;
        const __nv_bfloat16* src;
        uint32_t sz = 16;
        if (R < 256) {
            src = (R < 128 ? Ah : Al) + (size_t)(bm0 + (R & 127)) * lda;
        } else {
            int rg = bn0 + (R & 63);
            if (rg >= N) { rg = 0; sz = 0; }
            src = (R < 320 ? Bh : Bl) + (size_t)rg * K;
        }
        cp16(dst, src + ck * 32 + q * 8, sz);
    }
    asm volatile("cp.async.commit_group;");
}

__global__ __launch_bounds__(256) void gemm_mma(
    const __nv_bfloat16* __restrict__ Ah, const __nv_bfloat16* __restrict__ Al, int lda,
    const __nv_bfloat16* __restrict__ Bh, const __nv_bfloat16* __restrict__ Bl,
    const float* __restrict__ bias,
    float* __restrict__ Yf,
    __nv_bfloat16* __restrict__ Yh, __nv_bfloat16* __restrict__ Yl,
    int M, int N, int K)
{
    extern __shared__ __align__(16) char smem[];
    const uint32_t sb = smem_u32(smem);
    const int tid  = threadIdx.x;
    const int wid  = tid >> 5;
    const int lane = tid & 31;
    const int bn0  = blockIdx.x * 64;
    const int bm0  = blockIdx.y * 128;
    const int m0w  = (wid & 3) * 32;
    const int n0w  = (wid >> 2) * 32;

    float C[2][4][4];
#pragma unroll
    for (int mt = 0; mt < 2; mt++)
#pragma unroll
        for (int nt = 0; nt < 4; nt++)
#pragma unroll
            for (int v = 0; v < 4; v++) C[mt][nt][v] = 0.f;

    uint32_t aoffH[2], aoffL[2], boffH[2], boffL[2];
#pragma unroll
    for (int mt = 0; mt < 2; mt++) {
        uint32_t row = (uint32_t)(m0w + mt * 16 + (lane & 15));
        uint32_t kb  = (uint32_t)((lane >> 4) * 16);
        aoffH[mt] = sb + row * 80u + kb;
        aoffL[mt] = aoffH[mt] + 10240u;
    }
#pragma unroll
    for (int bt = 0; bt < 2; bt++) {
        uint32_t row = (uint32_t)(n0w + bt * 16 + (lane & 7) + ((lane >> 4) << 3));
        uint32_t kb  = (uint32_t)(((lane >> 3) & 1) * 16);
        boffH[bt] = sb + 20480u + row * 80u + kb;
        boffL[bt] = boffH[bt] + 5120u;
    }

    const int nk = K >> 5;
    g_loads(sb, tid, 0, 0, Ah, Al, lda, Bh, Bl, K, N, bm0, bn0);

    for (int t = 0; t < nk; t++) {
        const int buf = t & 1;
        if (t + 1 < nk) {
            g_loads(sb, tid, buf ^ 1, t + 1, Ah, Al, lda, Bh, Bl, K, N, bm0, bn0);
            asm volatile("cp.async.wait_group 1;" ::: "memory");
        } else {
            asm volatile("cp.async.wait_group 0;" ::: "memory");
        }
        __syncthreads();

        const uint32_t bofs = (uint32_t)buf * 30720u;
#pragma unroll
        for (int ks = 0; ks < 2; ks++) {
            const uint32_t ko = bofs + (uint32_t)ks * 32u;
            uint32_t ah[2][4], al[2][4], bh[4][2], bl[4][2];
#pragma unroll
            for (int mt = 0; mt < 2; mt++) {
                ldsm4(ah[mt][0], ah[mt][1], ah[mt][2], ah[mt][3], aoffH[mt] + ko);
                ldsm4(al[mt][0], al[mt][1], al[mt][2], al[mt][3], aoffL[mt] + ko);
            }
            ldsm4(bh[0][0], bh[0][1], bh[1][0], bh[1][1], boffH[0] + ko);
            ldsm4(bh[2][0], bh[2][1], bh[3][0], bh[3][1], boffH[1] + ko);
            ldsm4(bl[0][0], bl[0][1], bl[1][0], bl[1][1], boffL[0] + ko);
            ldsm4(bl[2][0], bl[2][1], bl[3][0], bl[3][1], boffL[1] + ko);
#pragma unroll
            for (int mt = 0; mt < 2; mt++)
#pragma unroll
                for (int nt = 0; nt < 4; nt++) {
                    mma16816(C[mt][nt], ah[mt], bh[nt]);
                    mma16816(C[mt][nt], ah[mt], bl[nt]);
                    mma16816(C[mt][nt], al[mt], bh[nt]);
                }
        }
        __syncthreads();
    }

#pragma unroll
    for (int mt = 0; mt < 2; mt++) {
        const int row = bm0 + m0w + mt * 16 + (lane >> 2);
#pragma unroll
        for (int nt = 0; nt < 4; nt++) {
            const int col = bn0 + n0w + nt * 8 + (lane & 3) * 2;
            if (col < N) {
                float b0 = bias ? bias[col]     : 0.f;
                float b1 = bias ? bias[col + 1] : 0.f;
                float v00 = C[mt][nt][0] + b0, v01 = C[mt][nt][1] + b1;
                float v10 = C[mt][nt][2] + b0, v11 = C[mt][nt][3] + b1;
                const size_t o0 = (size_t)row * N + col;
                const size_t o1 = (size_t)(row + 8) * N + col;
                if (Yf) {
                    *reinterpret_cast<float2*>(Yf + o0) = make_float2(v00, v01);
                    *reinterpret_cast<float2*>(Yf + o1) = make_float2(v10, v11);
                }
                if (Yh) {
                    __nv_bfloat16 h0, l0, h1, l1;
                    split_bf16(v00, h0, l0); split_bf16(v01, h1, l1);
                    *reinterpret_cast<__nv_bfloat162*>(Yh + o0) = __nv_bfloat162(h0, h1);
                    *reinterpret_cast<__nv_bfloat162*>(Yl + o0) = __nv_bfloat162(l0, l1);
                    split_bf16(v10, h0, l0); split_bf16(v11, h1, l1);
                    *reinterpret_cast<__nv_bfloat162*>(Yh + o1) = __nv_bfloat162(h0, h1);
                    *reinterpret_cast<__nv_bfloat162*>(Yl + o1) = __nv_bfloat162(l0, l1);
                }
            }
        }
    }
}

// ---------------- packed f32x2 helpers ----------------
__device__ __forceinline__ void ffma2(unsigned long long& d, unsigned long long a,
                                      unsigned long long b) {
    asm("fma.rn.f32x2 %0, %1, %2, %0;" : "+l"(d) : "l"(a), "l"(b));
}
__device__ __forceinline__ unsigned long long fma2_3(unsigned long long a,
                                                     unsigned long long b,
                                                     unsigned long long c) {
    unsigned long long d;
    asm("fma.rn.f32x2 %0, %1, %2, %3;" : "=l"(d) : "l"(a), "l"(b), "l"(c));
    return d;
}
__device__ __forceinline__ unsigned long long mul2(unsigned long long a,
                                                   unsigned long long b) {
    unsigned long long d;
    asm("mul.rn.f32x2 %0, %1, %2;" : "=l"(d) : "l"(a), "l"(b));
    return d;
}
__device__ __forceinline__ unsigned long long dup2(float x) {
    unsigned long long r;
    asm("mov.b64 %0, {%1, %1};" : "=l"(r) : "f"(x));
    return r;
}
__device__ __forceinline__ unsigned long long pk2(float x, float y) {
    unsigned long long r;
    asm("mov.b64 %0, {%1, %2};" : "=l"(r) : "f"(x), "f"(y));
    return r;
}
__device__ __forceinline__ float2 unpack2(unsigned long long v) {
    float2 f;
    asm("mov.b64 {%0, %1}, %2;" : "=f"(f.x), "=f"(f.y) : "l"(v));
    return f;
}

// ---------------- RMSNorm (no weight; folded into GEMM weights) ----------------
__global__ __launch_bounds__(256) void rmsnorm_now(
    const float* __restrict__ X,
    __nv_bfloat16* __restrict__ Yh, __nv_bfloat16* __restrict__ Yl, int rows)
{
    int row  = blockIdx.x * 8 + (threadIdx.x >> 5);
    int lane = threadIdx.x & 31;
    if (row >= rows) return;
    const float* xp = X + (size_t)row * DIM;
    float x[16];
    float ss = 0.f;
#pragma unroll
    for (int t = 0; t < 16; t++) { x[t] = xp[lane + t * 32]; ss += x[t] * x[t]; }
#pragma unroll
    for (int o = 16; o > 0; o >>= 1) ss += __shfl_xor_sync(0xffffffffu, ss, o);
    float rs = rsqrtf(ss * (1.0f / 512.0f) + RMS_EPS);
#pragma unroll
    for (int t = 0; t < 16; t++) {
        int c = lane + t * 32;
        __nv_bfloat16 h, l;
        split_bf16(x[t] * rs, h, l);
        Yh[(size_t)row * DIM + c] = h;
        Yl[(size_t)row * DIM + c] = l;
    }
}

// ---------------- Self attention on 4 compressed sequences ----------------
__global__ __launch_bounds__(256) void self_attn_kernel(
    const float* __restrict__ Q, int ldq, const float* __restrict__ KV,
    __nv_bfloat16* __restrict__ Oh, __nv_bfloat16* __restrict__ Ol)
{
    const int h     = blockIdx.x;
    const int batch = blockIdx.y;   // seq (g,b) 0..3
    const int i     = threadIdx.x;

    __shared__ __align__(16) float Ks[64][64];
    __shared__ __align__(16) float Vs[64][64];

    unsigned long long qp[32];
    {
        const float4* qq = reinterpret_cast<const float4*>(
            Q + ((size_t)(batch * 256 + i)) * ldq + h * 64);
#pragma unroll
        for (int t = 0; t < 16; t++) {
            float4 v = qq[t];
            qp[2 * t]     = pk2(v.x, v.y);
            qp[2 * t + 1] = pk2(v.z, v.w);
        }
    }

    float m = -1e30f, l = 0.f;
    unsigned long long acc[32];
#pragma unroll
    for (int t = 0; t < 32; t++) acc[t] = 0ull;

    for (int j0 = 0; j0 < 256; j0 += 64) {
        __syncthreads();
#pragma unroll
        for (int s = 0; s < 4; s++) {
            int u  = threadIdx.x + s * 256;
            int jr = u >> 4;
            int c4 = u & 15;
            const float* kp = KV + ((size_t)(batch * 256 + j0 + jr)) * 1024 + h * 64 + c4 * 4;
            *reinterpret_cast<float4*>(&Ks[jr][c4 * 4]) = *reinterpret_cast<const float4*>(kp);
            *reinterpret_cast<float4*>(&Vs[jr][c4 * 4]) = *reinterpret_cast<const float4*>(kp + 512);
        }
        __syncthreads();

        for (int j = 0; j < 64; j++) {
            const ulonglong2* kr = reinterpret_cast<const ulonglong2*>(Ks[j]);
            unsigned long long s0 = 0ull, s1 = 0ull;
#pragma unroll
            for (int t = 0; t < 8; t++) {
                ulonglong2 k0 = kr[2 * t];
                ulonglong2 k1 = kr[2 * t + 1];
                ffma2(s0, qp[4 * t + 0], k0.x);
                ffma2(s1, qp[4 * t + 1], k0.y);
                ffma2(s0, qp[4 * t + 2], k1.x);
                ffma2(s1, qp[4 * t + 3], k1.y);
            }
            float2 sa = unpack2(s0), sb = unpack2(s1);
            float s = (sa.x + sa.y) + (sb.x + sb.y);

            float mn = fmaxf(m, s);
            float f  = __expf(m - mn);
            float p  = __expf(s - mn);
            l = l * f + p;
            unsigned long long fd = dup2(f), pd = dup2(p);
            const ulonglong2* vr = reinterpret_cast<const ulonglong2*>(Vs[j]);
#pragma unroll
            for (int t = 0; t < 16; t++) {
                ulonglong2 vv = vr[t];
                acc[2 * t]     = fma2_3(acc[2 * t],     fd, mul2(vv.x, pd));
                acc[2 * t + 1] = fma2_3(acc[2 * t + 1], fd, mul2(vv.y, pd));
            }
            m = mn;
        }
    }

    float inv = 1.0f / l;
    size_t ob = ((size_t)(batch * 256 + i)) * 512 + h * 64;
#pragma unroll
    for (int t = 0; t < 32; t++) {
        float2 a = unpack2(acc[t]);
        __nv_bfloat16 hh, ll;
        split_bf16(a.x * inv, hh, ll);
        Oh[ob + 2 * t]     = hh; Ol[ob + 2 * t]     = ll;
        split_bf16(a.y * inv, hh, ll);
        Oh[ob + 2 * t + 1] = hh; Ol[ob + 2 * t + 1] = ll;
    }
}

// ---------------- Residual attention over UNIQUE messages with multiplicities ---
// query r = (g*2+b)*256+n, grid 1024 blocks; warp = head.
// uniques: u=0 tokens-kv (rows b*256+n indexed by g, weight 6);
//          u>=1: j=(u-1)/4, t=(u-1)%4, type=t>>1 (0=att,1=ret), g''=t&1, weight 3,
//          row (g''*2+g)*256+n of slab (j*2+type).
__global__ __launch_bounds__(256) void res_attn_kernel(
    const float* __restrict__ Qr, int ldq, const float* __restrict__ KVM, int Mu,
    __nv_bfloat16* __restrict__ Oh, __nv_bfloat16* __restrict__ Ol)
{
    const int r = blockIdx.x;
    const int g = r >> 9;
    const int n = r & 255;

    const int tid  = threadIdx.x;
    const int h    = tid >> 5;
    const int lane = tid & 31;

    __shared__ float qs[512];
    __shared__ float sim[8][16];

    qs[tid]       = Qr[(size_t)r * ldq + tid];
    qs[tid + 256] = Qr[(size_t)r * ldq + tid + 256];
    __syncthreads();

    float sc = -1e30f;
    const float* kpl = nullptr;
    float wl = 0.f;
    if (lane < Mu) {
        if (lane == 0) {
            kpl = KVM + ((size_t)(g * 256 + n)) * 1024;
            wl = 6.f;
        } else {
            int j = (lane - 1) >> 2, t = (lane - 1) & 3;
            int type = t >> 1, gpp = t & 1;
            kpl = KVM + 524288u
                + ((size_t)(j * 2 + type) << 20)
                + ((size_t)((gpp * 2 + g) * 256 + n)) * 1024;
            wl = 3.f;
        }
        const float4* k4 = reinterpret_cast<const float4*>(kpl + h * 64);
        const float4* q4 = reinterpret_cast<const float4*>(&qs[h * 64]);
        float s = 0.f;
#pragma unroll
        for (int t = 0; t < 16; t++) {
            float4 kk = k4[t];
            float4 qq = q4[t];
            s += qq.x * kk.x + qq.y * kk.y + qq.z * kk.z + qq.w * kk.w;
        }
        sc = s;
    }
    float mx = sc;
#pragma unroll
    for (int o = 16; o > 0; o >>= 1) mx = fmaxf(mx, __shfl_xor_sync(0xffffffffu, mx, o));
    float p = (lane < Mu) ? wl * __expf(sc - mx) : 0.f;
    if (lane < 16) sim[h][lane] = (lane < Mu) ? p : 0.f;
    float ls = p;
#pragma unroll
    for (int o = 16; o > 0; o >>= 1) ls += __shfl_xor_sync(0xffffffffu, ls, o);
    __syncwarp();

    float o0 = 0.f, o1 = 0.f;
    for (int u = 0; u < Mu; u++) {
        float a = sim[h][u];
        const float* vp;
        if (u == 0) {
            vp = KVM + ((size_t)(g * 256 + n)) * 1024 + 512;
        } else {
            int j = (u - 1) >> 2, t = (u - 1) & 3;
            int type = t >> 1, gpp = t & 1;
            vp = KVM + 524288u
               + ((size_t)(j * 2 + type) << 20)
               + ((size_t)((gpp * 2 + g) * 256 + n)) * 1024 + 512;
        }
        o0 += a * vp[h * 64 + lane];
        o1 += a * vp[h * 64 + lane + 32];
    }
    float inv = 1.0f / ls;
    __nv_bfloat16 hh, ll;
    split_bf16(o0 * inv, hh, ll);
    Oh[(size_t)r * 512 + h * 64 + lane] = hh;
    Ol[(size_t)r * 512 + h * 64 + lane] = ll;
    split_bf16(o1 * inv, hh, ll);
    Oh[(size_t)r * 512 + h * 64 + lane + 32] = hh;
    Ol[(size_t)r * 512 + h * 64 + lane + 32] = ll;
}

// ---------------- GEGLU from g_B (stride NBIG) -> split ACT ----------------
__global__ void geglu_split(const float* __restrict__ B,
                            __nv_bfloat16* __restrict__ Ah,
                            __nv_bfloat16* __restrict__ Al)
{
    int idx = blockIdx.x * blockDim.x + threadIdx.x;
    if (idx >= CROWS * DFFP) return;
    int row = idx / DFFP;
    int e   = idx - row * DFFP;
    float out = 0.f;
    if (e < DFF) {
        float s = B[(size_t)row * NBIG + 512 + e];
        float gg = B[(size_t)row * NBIG + 512 + DFF + e];
        out = s * (0.5f * gg * (1.0f + erff(gg * 0.70710678118654752440f)));
    }
    __nv_bfloat16 h, l;
    split_bf16(out, h, l);
    Ah[idx] = h;
    Al[idx] = l;
}

// ---------------- init: tokens -> compressed T (dup over g) ----------------
__global__ void init_tok(const float* __restrict__ tokens,
                         float* __restrict__ T,
                         __nv_bfloat16* __restrict__ Th, __nv_bfloat16* __restrict__ Tl)
{
    int idx = blockIdx.x * blockDim.x + threadIdx.x;
    if (idx >= CROWS * DIM) return;
    int d = idx & 511;
    int r = idx >> 9;          // (g*2+b)*256+n
    int n = r & 255;
    int b = (r >> 8) & 1;
    float v = tokens[((size_t)(b * 256 + n)) * 512 + d];
    T[idx] = v;
    __nv_bfloat16 h, l;
    split_bf16(v, h, l);
    Th[idx] = h; Tl[idx] = l;
}

// ---------------- weight preparation ----------------
__global__ void wbig_fill(const float* __restrict__ wq, const float* __restrict__ ffk,
                          const float* __restrict__ rq,
                          const float* __restrict__ anw, const float* __restrict__ fnw,
                          const float* __restrict__ rnw,
                          __nv_bfloat16* __restrict__ Wh, __nv_bfloat16* __restrict__ Wl)
{
    int idx = blockIdx.x * blockDim.x + threadIdx.x;
    if (idx >= NBIG * 512) return;
    int row = idx >> 9;
    int k   = idx & 511;
    float v = 0.f;
    if (row < 512)            v = wq [(size_t)row * 512 + k] * anw[k];
    else if (row < QRES_OFF)  v = ffk[(size_t)(row - 512) * 512 + k] * fnw[k];
    else if (row < 3754)      v = rq [(size_t)(row - QRES_OFF) * 512 + k] * rnw[k];
    __nv_bfloat16 h, l;
    split_bf16(v, h, l);
    Wh[idx] = h; Wl[idx] = l;
}

__global__ void bias_fill(const float* __restrict__ ffb, float* __restrict__ bias)
{
    int idx = blockIdx.x * blockDim.x + threadIdx.x;
    if (idx >= NBIG) return;
    bias[idx] = (idx >= 512 && idx < QRES_OFF) ? ffb[idx - 512] : 0.f;
}

__global__ void convw_kernel(const float* __restrict__ W,
                             __nv_bfloat16* __restrict__ Wh, __nv_bfloat16* __restrict__ Wl,
                             int count)
{
    int idx = blockIdx.x * blockDim.x + threadIdx.x;
    if (idx >= count) return;
    __nv_bfloat16 h, l;
    split_bf16(W[idx], h, l);
    Wh[idx] = h; Wl[idx] = l;
}

__global__ void convw_pad_kernel(const float* __restrict__ W,
                                 __nv_bfloat16* __restrict__ Wh, __nv_bfloat16* __restrict__ Wl)
{
    int idx = blockIdx.x * blockDim.x + threadIdx.x;
    if (idx >= DIM * DFFP) return;
    int row = idx / DFFP;
    int col = idx - row * DFFP;
    float v = (col < DFF) ? W[(size_t)row * DFF + col] : 0.f;
    __nv_bfloat16 h, l;
    split_bf16(v, h, l);
    Wh[idx] = h; Wl[idx] = l;
}

// wo [d,e] -> woT [e,d] split
__global__ void transw_kernel(const float* __restrict__ W,
                              __nv_bfloat16* __restrict__ Wh, __nv_bfloat16* __restrict__ Wl)
{
    int idx = blockIdx.x * blockDim.x + threadIdx.x;
    if (idx >= 512 * 512) return;
    int e = idx >> 9;
    int d = idx & 511;
    __nv_bfloat16 h, l;
    split_bf16(W[(size_t)d * 512 + e], h, l);
    Wh[idx] = h; Wl[idx] = l;
}

// ---------------- expand compressed T -> output (3072 rows) ----------------
__global__ void expand_kernel(const float* __restrict__ T, float* __restrict__ out)
{
    int idx = blockIdx.x * blockDim.x + threadIdx.x;
    if (idx >= 3072 * 512) return;
    int d  = idx & 511;
    int r2 = idx >> 9;          // (block*2+b)*256+n
    int n  = r2 & 255;
    int b  = (r2 >> 8) & 1;
    int block = r2 >> 9;
    int g = (2 * block + b) / 6;
    out[idx] = T[((size_t)((g * 2 + b) * 256 + n)) * 512 + d];
}

// -------------------------------- launch --------------------------------------
static inline void launch_gemm(const __nv_bfloat16* Ah, const __nv_bfloat16* Al, int lda,
                               const __nv_bfloat16* Bh, const __nv_bfloat16* Bl,
                               const float* bias, float* Yf,
                               __nv_bfloat16* Yh, __nv_bfloat16* Yl,
                               int M, int N, int K)
{
    dim3 grid((N + 63) / 64, M / 128);
    gemm_mma<<<grid, 256, GSMEM>>>(Ah, Al, lda, Bh, Bl, bias, Yf, Yh, Yl, M, N, K);
}

extern "C" void kernel_launch(void* const* d_in, const int* in_sizes, int n_in,
                              void* d_out, int out_size)
{
    const float* tokens      = (const float*)d_in[0];
    const float* attn_norm_w = (const float*)d_in[1];
    const float* attn_wq     = (const float*)d_in[2];
    const float* attn_wkv    = (const float*)d_in[3];
    const float* attn_wo     = (const float*)d_in[4];
    const float* ff_norm_w   = (const float*)d_in[5];
    const float* ff_keys_w   = (const float*)d_in[6];
    const float* ff_keys_b   = (const float*)d_in[7];
    const float* ff_values_w = (const float*)d_in[8];
    const float* ff_values_b = (const float*)d_in[9];
    const float* res_norm_w  = (const float*)d_in[10];
    const float* res_wq      = (const float*)d_in[11];
    const float* res_wkv     = (const float*)d_in[12];
    const float* res_wo      = (const float*)d_in[13];
    float* out = (float*)d_out;

    cudaFuncSetAttribute(gemm_mma, cudaFuncAttributeMaxDynamicSharedMemorySize, GSMEM);

    float *B, *T, *KV, *kvm, *bias;
    __nv_bfloat16 *XNh, *XNl, *XAh, *XAl, *ACTh, *ACTl, *RETh, *RETl, *XRh, *XRl, *Th, *Tl;
    __nv_bfloat16 *Wbigh, *Wbigl, *Wkvh, *Wkvl, *Rkvh, *Rkvl, *WoTh, *WoTl;
    __nv_bfloat16 *Wvph, *Wvpl, *Rwoh, *Rwol, *Cath, *Catl;
    cudaGetSymbolAddress((void**)&B,    g_B);
    cudaGetSymbolAddress((void**)&T,    g_T);
    cudaGetSymbolAddress((void**)&KV,   g_KV);
    cudaGetSymbolAddress((void**)&kvm,  g_kvm);
    cudaGetSymbolAddress((void**)&bias, g_bias);
    cudaGetSymbolAddress((void**)&XNh,  g_XNh);  cudaGetSymbolAddress((void**)&XNl, g_XNl);
    cudaGetSymbolAddress((void**)&XAh,  g_XAh);  cudaGetSymbolAddress((void**)&XAl, g_XAl);
    cudaGetSymbolAddress((void**)&ACTh, g_ACTh); cudaGetSymbolAddress((void**)&ACTl, g_ACTl);
    cudaGetSymbolAddress((void**)&RETh, g_RETh); cudaGetSymbolAddress((void**)&RETl, g_RETl);
    cudaGetSymbolAddress((void**)&XRh,  g_XRh);  cudaGetSymbolAddress((void**)&XRl, g_XRl);
    cudaGetSymbolAddress((void**)&Th,   g_Th);   cudaGetSymbolAddress((void**)&Tl,  g_Tl);
    cudaGetSymbolAddress((void**)&Wbigh, g_Wbigh); cudaGetSymbolAddress((void**)&Wbigl, g_Wbigl);
    cudaGetSymbolAddress((void**)&Wkvh, g_Wkvh); cudaGetSymbolAddress((void**)&Wkvl, g_Wkvl);
    cudaGetSymbolAddress((void**)&Rkvh, g_Rkvh); cudaGetSymbolAddress((void**)&Rkvl, g_Rkvl);
    cudaGetSymbolAddress((void**)&WoTh, g_WoTh); cudaGetSymbolAddress((void**)&WoTl, g_WoTl);
    cudaGetSymbolAddress((void**)&Wvph, g_Wvph); cudaGetSymbolAddress((void**)&Wvpl, g_Wvpl);
    cudaGetSymbolAddress((void**)&Rwoh, g_Rwoh); cudaGetSymbolAddress((void**)&Rwol, g_Rwol);
    cudaGetSymbolAddress((void**)&Cath, g_Cath); cudaGetSymbolAddress((void**)&Catl, g_Catl);

    // ---- precompute: weights ----
    wbig_fill<<<(NBIG * 512 + 255) / 256, 256>>>(attn_wq, ff_keys_w, res_wq,
                                                 attn_norm_w, ff_norm_w, res_norm_w,
                                                 Wbigh, Wbigl);
    bias_fill<<<(NBIG + 255) / 256, 256>>>(ff_keys_b, bias);
    convw_kernel<<<(1024 * 512 + 255) / 256, 256>>>(attn_wkv, Wkvh, Wkvl, 1024 * 512);
    convw_kernel<<<(1024 * 512 + 255) / 256, 256>>>(res_wkv,  Rkvh, Rkvl, 1024 * 512);
    convw_kernel<<<(512 * 512 + 255) / 256, 256>>>(res_wo,   Rwoh, Rwol, 512 * 512);
    transw_kernel<<<(512 * 512 + 255) / 256, 256>>>(attn_wo, WoTh, WoTl);
    convw_pad_kernel<<<(DIM * DFFP + 255) / 256, 256>>>(ff_values_w, Wvph, Wvpl);

    // C_att = res_wkv @ attn_wo  (split output)
    launch_gemm(Rkvh, Rkvl, 512, WoTh, WoTl, nullptr,
                nullptr, Cath, Catl, 1024, 512, 512);

    // tokens -> compressed T; tokens-kv (rows 0..511 of Th are tokens)
    init_tok<<<(CROWS * DIM + 255) / 256, 256>>>(tokens, T, Th, Tl);
    launch_gemm(Th, Tl, 512, Rkvh, Rkvl, nullptr,
                kvm, nullptr, nullptr, 512, 1024, 512);

    for (int e = 0; e < 3; e++) {
        float* kv_att = kvm + 524288 + (size_t)(e * 2 + 0) * 1048576;
        float* kv_ret = kvm + 524288 + (size_t)(e * 2 + 1) * 1048576;

        // normalized input (weight folded into Wbig)
        rmsnorm_now<<<CROWS / 8, 256>>>(T, XNh, XNl, CROWS);

        // mega-GEMM: [Q | H | Qres]
        launch_gemm(XNh, XNl, 512, Wbigh, Wbigl, bias,
                    B, nullptr, nullptr, CROWS, NBIG, 512);

        // self-attention kv on raw tokens
        launch_gemm(Th, Tl, 512, Wkvh, Wkvl, nullptr,
                    KV, nullptr, nullptr, CROWS, 1024, 512);
        self_attn_kernel<<<dim3(HEADS, 4), 256>>>(B, NBIG, KV, XAh, XAl);

        // attended kv directly (skip WO): kv_att = XA @ C_att^T
        launch_gemm(XAh, XAl, 512, Cath, Catl, nullptr,
                    kv_att, nullptr, nullptr, CROWS, 1024, 512);

        // feedforward: geglu from B, then values GEMM, then kv
        geglu_split<<<(CROWS * DFFP + 255) / 256, 256>>>(B, ACTh, ACTl);
        launch_gemm(ACTh, ACTl, DFFP, Wvph, Wvpl, ff_values_b,
                    nullptr, RETh, RETl, CROWS, 512, DFFP);
        launch_gemm(RETh, RETl, 512, Rkvh, Rkvl, nullptr,
                    kv_ret, nullptr, nullptr, CROWS, 1024, 512);

        // residual pooled attention over unique messages
        int Mu = 1 + 4 * (e + 1);
        res_attn_kernel<<<CROWS, 256>>>(B + QRES_OFF, NBIG, kvm, Mu, XRh, XRl);
        launch_gemm(XRh, XRl, 512, Rwoh, Rwol, nullptr,
                    T, Th, Tl, CROWS, 512, 512);
    }

    expand_kernel<<<(3072 * 512 + 255) / 256, 256>>>(T, out);
}

// round 7
// speedup vs baseline: 4.3661x; 1.2448x over previous
#include <cuda_runtime.h>
#include <cuda_bf16.h>
#include <math.h>
#include <stdint.h>

#define DIM     512
#define HEADS   8
#define DFF     1365
#define DFF2    2730
#define DFFP    1408            // DFF padded (K multiple of 32)
#define CROWS   1024            // compressed rows: (g,b,n)
#define NBIG    3756            // 512 + 2730 + 512 + 2 align pad
#define QRES_OFF 3242           // 512 + 2730
#define RMS_EPS 1.1920929e-07f

// ---------------- scratch (device globals) ----------------
static __device__ float g_B   [CROWS * NBIG];     // [Q | H | Qres]
static __device__ float g_T   [CROWS * DIM];
static __device__ float g_KV  [CROWS * 1024];
static __device__ float g_kvm [512 * 1024 + 6 * 1024 * 1024]; // tok + (att,ret)x3
static __device__ float g_bias[NBIG];
static __device__ float g_pacc[128 * 64 * 256];   // attention partials
static __device__ float g_pml [128 * 2 * 256];

static __device__ __nv_bfloat16 g_XNh[CROWS * DIM],  g_XNl[CROWS * DIM];
static __device__ __nv_bfloat16 g_XAh[CROWS * DIM],  g_XAl[CROWS * DIM];
static __device__ __nv_bfloat16 g_ACTh[CROWS * DFFP], g_ACTl[CROWS * DFFP];
static __device__ __nv_bfloat16 g_RETh[CROWS * DIM], g_RETl[CROWS * DIM];
static __device__ __nv_bfloat16 g_XRh[CROWS * DIM],  g_XRl[CROWS * DIM];
static __device__ __nv_bfloat16 g_Th [CROWS * DIM],  g_Tl [CROWS * DIM];

static __device__ __nv_bfloat16 g_Wbigh[NBIG * 512], g_Wbigl[NBIG * 512];
static __device__ __nv_bfloat16 g_Wkvh[1024 * 512],  g_Wkvl[1024 * 512];
static __device__ __nv_bfloat16 g_Rkvh[1024 * 512],  g_Rkvl[1024 * 512];
static __device__ __nv_bfloat16 g_WoTh[512 * 512],   g_WoTl[512 * 512];
static __device__ __nv_bfloat16 g_Wvph[512 * DFFP],  g_Wvpl[512 * DFFP];
static __device__ __nv_bfloat16 g_Rwoh[512 * 512],   g_Rwol[512 * 512];
static __device__ __nv_bfloat16 g_Cath[1024 * 512],  g_Catl[1024 * 512];

// ---------------- helpers ----------------
__device__ __forceinline__ void split_bf16(float v, __nv_bfloat16& h, __nv_bfloat16& l) {
    h = __float2bfloat16(v);
    l = __float2bfloat16(v - __bfloat162float(h));
}
__device__ __forceinline__ uint32_t smem_u32(const void* p) {
    uint32_t a;
    asm("{ .reg .u64 t; cvta.to.shared.u64 t, %1; cvt.u32.u64 %0, t; }" : "=r"(a) : "l"(p));
    return a;
}
__device__ __forceinline__ void cp16(uint32_t dst, const void* src, uint32_t sz) {
    asm volatile("cp.async.cg.shared.global [%0], [%1], 16, %2;"
                 :: "r"(dst), "l"(src), "r"(sz));
}
__device__ __forceinline__ void ldsm4(uint32_t& r0, uint32_t& r1, uint32_t& r2,
                                      uint32_t& r3, uint32_t addr) {
    asm volatile("ldmatrix.sync.aligned.m8n8.x4.shared.b16 {%0,%1,%2,%3}, [%4];"
                 : "=r"(r0), "=r"(r1), "=r"(r2), "=r"(r3) : "r"(addr));
}
__device__ __forceinline__ void mma16816(float* c, const uint32_t* a, const uint32_t* b) {
    asm volatile(
        "mma.sync.aligned.m16n8k16.row.col.f32.bf16.bf16.f32 "
        "{%0,%1,%2,%3}, {%4,%5,%6,%7}, {%8,%9}, {%0,%1,%2,%3};"
        : "+f"(c[0]), "+f"(c[1]), "+f"(c[2]), "+f"(c[3])
        : "r"(a[0]), "r"(a[1]), "r"(a[2]), "r"(a[3]), "r"(b[0]), "r"(b[1]));
}

// ---------------- tensor-core split-bf16 GEMM --------------------------
#define GSMEM 61440

__device__ __forceinline__ void g_loads(
    uint32_t sb, int tid, int buf, int ck,
    const __nv_bfloat16* Ah, const __nv_bfloat16* Al, int lda,
    const __nv_bfloat16* Bh, const __nv_bfloat16* Bl,
    int K, int N, int bm0, int bn0)
{
    const uint32_t bufbase = sb + (uint32_t)buf * 30720u;
#pragma unroll
    for (int i = 0; i < 6; i++) {
        int c = tid + i * 256;
        int R = c >> 2;
        int q = c & 3;
        uint32_t dst = bufbase + (uint32_t)R * 80u + (uint32_t)q * 16u;
        const __nv_bfloat16* src;
        uint32_t sz = 16;
        if (R < 256) {
            src = (R < 128 ? Ah : Al) + (size_t)(bm0 + (R & 127)) * lda;
        } else {
            int rg = bn0 + (R & 63);
            if (rg >= N) { rg = 0; sz = 0; }
            src = (R < 320 ? Bh : Bl) + (size_t)rg * K;
        }
        cp16(dst, src + ck * 32 + q * 8, sz);
    }
    asm volatile("cp.async.commit_group;");
}

__global__ __launch_bounds__(256) void gemm_mma(
    const __nv_bfloat16* __restrict__ Ah, const __nv_bfloat16* __restrict__ Al, int lda,
    const __nv_bfloat16* __restrict__ Bh, const __nv_bfloat16* __restrict__ Bl,
    const float* __restrict__ bias,
    float* __restrict__ Yf,
    __nv_bfloat16* __restrict__ Yh, __nv_bfloat16* __restrict__ Yl,
    int M, int N, int K)
{
    extern __shared__ __align__(16) char smem[];
    const uint32_t sb = smem_u32(smem);
    const int tid  = threadIdx.x;
    const int wid  = tid >> 5;
    const int lane = tid & 31;
    const int bn0  = blockIdx.x * 64;
    const int bm0  = blockIdx.y * 128;
    const int m0w  = (wid & 3) * 32;
    const int n0w  = (wid >> 2) * 32;

    float C[2][4][4];
#pragma unroll
    for (int mt = 0; mt < 2; mt++)
#pragma unroll
        for (int nt = 0; nt < 4; nt++)
#pragma unroll
            for (int v = 0; v < 4; v++) C[mt][nt][v] = 0.f;

    uint32_t aoffH[2], aoffL[2], boffH[2], boffL[2];
#pragma unroll
    for (int mt = 0; mt < 2; mt++) {
        uint32_t row = (uint32_t)(m0w + mt * 16 + (lane & 15));
        uint32_t kb  = (uint32_t)((lane >> 4) * 16);
        aoffH[mt] = sb + row * 80u + kb;
        aoffL[mt] = aoffH[mt] + 10240u;
    }
#pragma unroll
    for (int bt = 0; bt < 2; bt++) {
        uint32_t row = (uint32_t)(n0w + bt * 16 + (lane & 7) + ((lane >> 4) << 3));
        uint32_t kb  = (uint32_t)(((lane >> 3) & 1) * 16);
        boffH[bt] = sb + 20480u + row * 80u + kb;
        boffL[bt] = boffH[bt] + 5120u;
    }

    const int nk = K >> 5;
    g_loads(sb, tid, 0, 0, Ah, Al, lda, Bh, Bl, K, N, bm0, bn0);

    for (int t = 0; t < nk; t++) {
        const int buf = t & 1;
        if (t + 1 < nk) {
            g_loads(sb, tid, buf ^ 1, t + 1, Ah, Al, lda, Bh, Bl, K, N, bm0, bn0);
            asm volatile("cp.async.wait_group 1;" ::: "memory");
        } else {
            asm volatile("cp.async.wait_group 0;" ::: "memory");
        }
        __syncthreads();

        const uint32_t bofs = (uint32_t)buf * 30720u;
#pragma unroll
        for (int ks = 0; ks < 2; ks++) {
            const uint32_t ko = bofs + (uint32_t)ks * 32u;
            uint32_t ah[2][4], al[2][4], bh[4][2], bl[4][2];
#pragma unroll
            for (int mt = 0; mt < 2; mt++) {
                ldsm4(ah[mt][0], ah[mt][1], ah[mt][2], ah[mt][3], aoffH[mt] + ko);
                ldsm4(al[mt][0], al[mt][1], al[mt][2], al[mt][3], aoffL[mt] + ko);
            }
            ldsm4(bh[0][0], bh[0][1], bh[1][0], bh[1][1], boffH[0] + ko);
            ldsm4(bh[2][0], bh[2][1], bh[3][0], bh[3][1], boffH[1] + ko);
            ldsm4(bl[0][0], bl[0][1], bl[1][0], bl[1][1], boffL[0] + ko);
            ldsm4(bl[2][0], bl[2][1], bl[3][0], bl[3][1], boffL[1] + ko);
#pragma unroll
            for (int mt = 0; mt < 2; mt++)
#pragma unroll
                for (int nt = 0; nt < 4; nt++) {
                    mma16816(C[mt][nt], ah[mt], bh[nt]);
                    mma16816(C[mt][nt], ah[mt], bl[nt]);
                    mma16816(C[mt][nt], al[mt], bh[nt]);
                }
        }
        __syncthreads();
    }

#pragma unroll
    for (int mt = 0; mt < 2; mt++) {
        const int row = bm0 + m0w + mt * 16 + (lane >> 2);
#pragma unroll
        for (int nt = 0; nt < 4; nt++) {
            const int col = bn0 + n0w + nt * 8 + (lane & 3) * 2;
            if (col < N) {
                float b0 = bias ? bias[col]     : 0.f;
                float b1 = bias ? bias[col + 1] : 0.f;
                float v00 = C[mt][nt][0] + b0, v01 = C[mt][nt][1] + b1;
                float v10 = C[mt][nt][2] + b0, v11 = C[mt][nt][3] + b1;
                const size_t o0 = (size_t)row * N + col;
                const size_t o1 = (size_t)(row + 8) * N + col;
                if (Yf) {
                    *reinterpret_cast<float2*>(Yf + o0) = make_float2(v00, v01);
                    *reinterpret_cast<float2*>(Yf + o1) = make_float2(v10, v11);
                }
                if (Yh) {
                    __nv_bfloat16 h0, l0, h1, l1;
                    split_bf16(v00, h0, l0); split_bf16(v01, h1, l1);
                    *reinterpret_cast<__nv_bfloat162*>(Yh + o0) = __nv_bfloat162(h0, h1);
                    *reinterpret_cast<__nv_bfloat162*>(Yl + o0) = __nv_bfloat162(l0, l1);
                    split_bf16(v10, h0, l0); split_bf16(v11, h1, l1);
                    *reinterpret_cast<__nv_bfloat162*>(Yh + o1) = __nv_bfloat162(h0, h1);
                    *reinterpret_cast<__nv_bfloat162*>(Yl + o1) = __nv_bfloat162(l0, l1);
                }
            }
        }
    }
}

// ---------------- packed f32x2 helpers ----------------
__device__ __forceinline__ void ffma2(unsigned long long& d, unsigned long long a,
                                      unsigned long long b) {
    asm("fma.rn.f32x2 %0, %1, %2, %0;" : "+l"(d) : "l"(a), "l"(b));
}
__device__ __forceinline__ unsigned long long fma2_3(unsigned long long a,
                                                     unsigned long long b,
                                                     unsigned long long c) {
    unsigned long long d;
    asm("fma.rn.f32x2 %0, %1, %2, %3;" : "=l"(d) : "l"(a), "l"(b), "l"(c));
    return d;
}
__device__ __forceinline__ unsigned long long mul2(unsigned long long a,
                                                   unsigned long long b) {
    unsigned long long d;
    asm("mul.rn.f32x2 %0, %1, %2;" : "=l"(d) : "l"(a), "l"(b));
    return d;
}
__device__ __forceinline__ unsigned long long dup2(float x) {
    unsigned long long r;
    asm("mov.b64 %0, {%1, %1};" : "=l"(r) : "f"(x));
    return r;
}
__device__ __forceinline__ unsigned long long pk2(float x, float y) {
    unsigned long long r;
    asm("mov.b64 %0, {%1, %2};" : "=l"(r) : "f"(x), "f"(y));
    return r;
}
__device__ __forceinline__ float2 unpack2(unsigned long long v) {
    float2 f;
    asm("mov.b64 {%0, %1}, %2;" : "=f"(f.x), "=f"(f.y) : "l"(v));
    return f;
}

// ---------------- RMSNorm (weight folded into GEMM weights) ----------------
__global__ __launch_bounds__(256) void rmsnorm_now(
    const float* __restrict__ X,
    __nv_bfloat16* __restrict__ Yh, __nv_bfloat16* __restrict__ Yl, int rows)
{
    int row  = blockIdx.x * 8 + (threadIdx.x >> 5);
    int lane = threadIdx.x & 31;
    if (row >= rows) return;
    const float* xp = X + (size_t)row * DIM;
    float x[16];
    float ss = 0.f;
#pragma unroll
    for (int t = 0; t < 16; t++) { x[t] = xp[lane + t * 32]; ss += x[t] * x[t]; }
#pragma unroll
    for (int o = 16; o > 0; o >>= 1) ss += __shfl_xor_sync(0xffffffffu, ss, o);
    float rs = rsqrtf(ss * (1.0f / 512.0f) + RMS_EPS);
#pragma unroll
    for (int t = 0; t < 16; t++) {
        int c = lane + t * 32;
        __nv_bfloat16 h, l;
        split_bf16(x[t] * rs, h, l);
        Yh[(size_t)row * DIM + c] = h;
        Yl[(size_t)row * DIM + c] = l;
    }
}

// ---------------- Self attention, split over 4 key-chunks ----------------
// grid (HEADS, nbatch, 4). Each block: 64 keys, 256 queries (1/thread).
__global__ __launch_bounds__(256) void self_attn_part(
    const float* __restrict__ Q, int ldq, const float* __restrict__ KV,
    float* __restrict__ pacc, float* __restrict__ pml, int nbatch)
{
    const int h     = blockIdx.x;
    const int batch = blockIdx.y;
    const int jc    = blockIdx.z;
    const int i     = threadIdx.x;
    const int j0    = jc * 64;

    __shared__ __align__(16) float Ks[64][64];
    __shared__ __align__(16) float Vs[64][64];

    unsigned long long qp[32];
    {
        const float4* qq = reinterpret_cast<const float4*>(
            Q + ((size_t)(batch * 256 + i)) * ldq + h * 64);
#pragma unroll
        for (int t = 0; t < 16; t++) {
            float4 v = qq[t];
            qp[2 * t]     = pk2(v.x, v.y);
            qp[2 * t + 1] = pk2(v.z, v.w);
        }
    }

#pragma unroll
    for (int s = 0; s < 4; s++) {
        int u  = threadIdx.x + s * 256;
        int jr = u >> 4;
        int c4 = u & 15;
        const float* kp = KV + ((size_t)(batch * 256 + j0 + jr)) * 1024 + h * 64 + c4 * 4;
        *reinterpret_cast<float4*>(&Ks[jr][c4 * 4]) = *reinterpret_cast<const float4*>(kp);
        *reinterpret_cast<float4*>(&Vs[jr][c4 * 4]) = *reinterpret_cast<const float4*>(kp + 512);
    }
    __syncthreads();

    float m = -1e30f, l = 0.f;
    unsigned long long acc[32];
#pragma unroll
    for (int t = 0; t < 32; t++) acc[t] = 0ull;

    for (int j = 0; j < 64; j++) {
        const ulonglong2* kr = reinterpret_cast<const ulonglong2*>(Ks[j]);
        unsigned long long s0 = 0ull, s1 = 0ull;
#pragma unroll
        for (int t = 0; t < 8; t++) {
            ulonglong2 k0 = kr[2 * t];
            ulonglong2 k1 = kr[2 * t + 1];
            ffma2(s0, qp[4 * t + 0], k0.x);
            ffma2(s1, qp[4 * t + 1], k0.y);
            ffma2(s0, qp[4 * t + 2], k1.x);
            ffma2(s1, qp[4 * t + 3], k1.y);
        }
        float2 sa = unpack2(s0), sb = unpack2(s1);
        float s = (sa.x + sa.y) + (sb.x + sb.y);

        float mn = fmaxf(m, s);
        float f  = __expf(m - mn);
        float p  = __expf(s - mn);
        l = l * f + p;
        unsigned long long fd = dup2(f), pd = dup2(p);
        const ulonglong2* vr = reinterpret_cast<const ulonglong2*>(Vs[j]);
#pragma unroll
        for (int t = 0; t < 16; t++) {
            ulonglong2 vv = vr[t];
            acc[2 * t]     = fma2_3(acc[2 * t],     fd, mul2(vv.x, pd));
            acc[2 * t + 1] = fma2_3(acc[2 * t + 1], fd, mul2(vv.y, pd));
        }
        m = mn;
    }

    const int bl = (jc * nbatch + batch) * HEADS + h;
    float* pa = pacc + ((size_t)bl * 64) * 256;
#pragma unroll
    for (int t = 0; t < 32; t++) {
        float2 a = unpack2(acc[t]);
        pa[(2 * t) * 256 + i]     = a.x;
        pa[(2 * t + 1) * 256 + i] = a.y;
    }
    pml[(bl * 2 + 0) * 256 + i] = m;
    pml[(bl * 2 + 1) * 256 + i] = l;
}

// combine: one thread per (batch, h, i)
__global__ __launch_bounds__(256) void self_attn_combine(
    const float* __restrict__ pacc, const float* __restrict__ pml,
    __nv_bfloat16* __restrict__ Oh, __nv_bfloat16* __restrict__ Ol, int nbatch)
{
    int idx   = blockIdx.x * 256 + threadIdx.x;
    int i     = idx & 255;
    int h     = (idx >> 8) & 7;
    int batch = idx >> 11;

    float mc[4], lc[4];
    float M = -1e30f;
#pragma unroll
    for (int c = 0; c < 4; c++) {
        int bl = (c * nbatch + batch) * HEADS + h;
        mc[c] = pml[(bl * 2 + 0) * 256 + i];
        lc[c] = pml[(bl * 2 + 1) * 256 + i];
        M = fmaxf(M, mc[c]);
    }
    float w[4];
    float L = 0.f;
#pragma unroll
    for (int c = 0; c < 4; c++) { w[c] = __expf(mc[c] - M); L += lc[c] * w[c]; }
    float inv = 1.0f / L;

    size_t ob = ((size_t)(batch * 256 + i)) * 512 + h * 64;
#pragma unroll
    for (int t = 0; t < 64; t++) {
        float o = 0.f;
#pragma unroll
        for (int c = 0; c < 4; c++) {
            int bl = (c * nbatch + batch) * HEADS + h;
            o += w[c] * pacc[((size_t)bl * 64 + t) * 256 + i];
        }
        __nv_bfloat16 hh, ll;
        split_bf16(o * inv, hh, ll);
        Oh[ob + t] = hh;
        Ol[ob + t] = ll;
    }
}

// ---------------- Residual attention over unique messages ----------------
// u=0: tokens, row g*256+n, w=6.  u=1,2: e0 att/ret slabs (512 rows), row g*256+n, w=6.
// u>=3: j=1+(u-3)/4, t=(u-3)%4, type=t>>1, gpp=t&1; slab j*2+type, row (gpp*2+g)*256+n, w=3.
__device__ __forceinline__ const float* msg_ptr(
    const float* KVM, int u, int g, int n, float* w)
{
    if (u == 0) { *w = 6.f; return KVM + ((size_t)(g * 256 + n)) * 1024; }
    if (u <= 2) { *w = 6.f;
        return KVM + 524288u + (size_t)(u - 1) * 1048576u + ((size_t)(g * 256 + n)) * 1024; }
    int j = 1 + ((u - 3) >> 2), t = (u - 3) & 3;
    int type = t >> 1, gpp = t & 1;
    *w = 3.f;
    return KVM + 524288u + ((size_t)(j * 2 + type)) * 1048576u
         + ((size_t)((gpp * 2 + g) * 256 + n)) * 1024;
}

__global__ __launch_bounds__(256) void res_attn_kernel(
    const float* __restrict__ Qr, int ldq, int qmask,
    const float* __restrict__ KVM, int Mu,
    __nv_bfloat16* __restrict__ Oh, __nv_bfloat16* __restrict__ Ol)
{
    const int r = blockIdx.x;
    const int g = r >> 9;
    const int n = r & 255;
    const int qrow = r & qmask;

    const int tid  = threadIdx.x;
    const int h    = tid >> 5;
    const int lane = tid & 31;

    __shared__ float qs[512];
    __shared__ float sim[8][16];

    qs[tid]       = Qr[(size_t)qrow * ldq + tid];
    qs[tid + 256] = Qr[(size_t)qrow * ldq + tid + 256];
    __syncthreads();

    float sc = -1e30f;
    float wl = 0.f;
    if (lane < Mu) {
        const float* kpl = msg_ptr(KVM, lane, g, n, &wl);
        const float4* k4 = reinterpret_cast<const float4*>(kpl + h * 64);
        const float4* q4 = reinterpret_cast<const float4*>(&qs[h * 64]);
        float s = 0.f;
#pragma unroll
        for (int t = 0; t < 16; t++) {
            float4 kk = k4[t];
            float4 qq = q4[t];
            s += qq.x * kk.x + qq.y * kk.y + qq.z * kk.z + qq.w * kk.w;
        }
        sc = s;
    }
    float mx = sc;
#pragma unroll
    for (int o = 16; o > 0; o >>= 1) mx = fmaxf(mx, __shfl_xor_sync(0xffffffffu, mx, o));
    float p = (lane < Mu) ? wl * __expf(sc - mx) : 0.f;
    if (lane < 16) sim[h][lane] = p;
    float ls = p;
#pragma unroll
    for (int o = 16; o > 0; o >>= 1) ls += __shfl_xor_sync(0xffffffffu, ls, o);
    __syncwarp();

    float o0 = 0.f, o1 = 0.f;
    for (int u = 0; u < Mu; u++) {
        float a = sim[h][u];
        float dummy;
        const float* vp = msg_ptr(KVM, u, g, n, &dummy) + 512;
        o0 += a * vp[h * 64 + lane];
        o1 += a * vp[h * 64 + lane + 32];
    }
    float inv = 1.0f / ls;
    __nv_bfloat16 hh, ll;
    split_bf16(o0 * inv, hh, ll);
    Oh[(size_t)r * 512 + h * 64 + lane] = hh;
    Ol[(size_t)r * 512 + h * 64 + lane] = ll;
    split_bf16(o1 * inv, hh, ll);
    Oh[(size_t)r * 512 + h * 64 + lane + 32] = hh;
    Ol[(size_t)r * 512 + h * 64 + lane + 32] = ll;
}

// ---------------- GEGLU from g_B (stride NBIG) -> split ACT ----------------
__global__ void geglu_split(const float* __restrict__ B,
                            __nv_bfloat16* __restrict__ Ah,
                            __nv_bfloat16* __restrict__ Al, int count)
{
    int idx = blockIdx.x * blockDim.x + threadIdx.x;
    if (idx >= count) return;
    int row = idx / DFFP;
    int e   = idx - row * DFFP;
    float out = 0.f;
    if (e < DFF) {
        float s = B[(size_t)row * NBIG + 512 + e];
        float gg = B[(size_t)row * NBIG + 512 + DFF + e];
        out = s * (0.5f * gg * (1.0f + erff(gg * 0.70710678118654752440f)));
    }
    __nv_bfloat16 h, l;
    split_bf16(out, h, l);
    Ah[idx] = h;
    Al[idx] = l;
}

// ---------------- init: tokens -> compressed T (dup over g) ----------------
__global__ void init_tok(const float* __restrict__ tokens,
                         float* __restrict__ T,
                         __nv_bfloat16* __restrict__ Th, __nv_bfloat16* __restrict__ Tl)
{
    int idx = blockIdx.x * blockDim.x + threadIdx.x;
    if (idx >= CROWS * DIM) return;
    int d = idx & 511;
    int r = idx >> 9;
    int n = r & 255;
    int b = (r >> 8) & 1;
    float v = tokens[((size_t)(b * 256 + n)) * 512 + d];
    T[idx] = v;
    __nv_bfloat16 h, l;
    split_bf16(v, h, l);
    Th[idx] = h; Tl[idx] = l;
}

// ---------------- weight preparation ----------------
__global__ void wbig_fill(const float* __restrict__ wq, const float* __restrict__ ffk,
                          const float* __restrict__ rq,
                          const float* __restrict__ anw, const float* __restrict__ fnw,
                          const float* __restrict__ rnw,
                          __nv_bfloat16* __restrict__ Wh, __nv_bfloat16* __restrict__ Wl)
{
    int idx = blockIdx.x * blockDim.x + threadIdx.x;
    if (idx >= NBIG * 512) return;
    int row = idx >> 9;
    int k   = idx & 511;
    float v = 0.f;
    if (row < 512)            v = wq [(size_t)row * 512 + k] * anw[k];
    else if (row < QRES_OFF)  v = ffk[(size_t)(row - 512) * 512 + k] * fnw[k];
    else if (row < 3754)      v = rq [(size_t)(row - QRES_OFF) * 512 + k] * rnw[k];
    __nv_bfloat16 h, l;
    split_bf16(v, h, l);
    Wh[idx] = h; Wl[idx] = l;
}

__global__ void bias_fill(const float* __restrict__ ffb, float* __restrict__ bias)
{
    int idx = blockIdx.x * blockDim.x + threadIdx.x;
    if (idx >= NBIG) return;
    bias[idx] = (idx >= 512 && idx < QRES_OFF) ? ffb[idx - 512] : 0.f;
}

__global__ void convw_kernel(const float* __restrict__ W,
                             __nv_bfloat16* __restrict__ Wh, __nv_bfloat16* __restrict__ Wl,
                             int count)
{
    int idx = blockIdx.x * blockDim.x + threadIdx.x;
    if (idx >= count) return;
    __nv_bfloat16 h, l;
    split_bf16(W[idx], h, l);
    Wh[idx] = h; Wl[idx] = l;
}

__global__ void convw_pad_kernel(const float* __restrict__ W,
                                 __nv_bfloat16* __restrict__ Wh, __nv_bfloat16* __restrict__ Wl)
{
    int idx = blockIdx.x * blockDim.x + threadIdx.x;
    if (idx >= DIM * DFFP) return;
    int row = idx / DFFP;
    int col = idx - row * DFFP;
    float v = (col < DFF) ? W[(size_t)row * DFF + col] : 0.f;
    __nv_bfloat16 h, l;
    split_bf16(v, h, l);
    Wh[idx] = h; Wl[idx] = l;
}

__global__ void transw_kernel(const float* __restrict__ W,
                              __nv_bfloat16* __restrict__ Wh, __nv_bfloat16* __restrict__ Wl)
{
    int idx = blockIdx.x * blockDim.x + threadIdx.x;
    if (idx >= 512 * 512) return;
    int e = idx >> 9;
    int d = idx & 511;
    __nv_bfloat16 h, l;
    split_bf16(W[(size_t)d * 512 + e], h, l);
    Wh[idx] = h; Wl[idx] = l;
}

// ---------------- expand compressed T -> output (3072 rows) ----------------
__global__ void expand_kernel(const float* __restrict__ T, float* __restrict__ out)
{
    int idx = blockIdx.x * blockDim.x + threadIdx.x;
    if (idx >= 3072 * 512) return;
    int d  = idx & 511;
    int r2 = idx >> 9;
    int n  = r2 & 255;
    int b  = (r2 >> 8) & 1;
    int block = r2 >> 9;
    int g = (2 * block + b) / 6;
    out[idx] = T[((size_t)((g * 2 + b) * 256 + n)) * 512 + d];
}

// -------------------------------- launch --------------------------------------
static inline void launch_gemm(const __nv_bfloat16* Ah, const __nv_bfloat16* Al, int lda,
                               const __nv_bfloat16* Bh, const __nv_bfloat16* Bl,
                               const float* bias, float* Yf,
                               __nv_bfloat16* Yh, __nv_bfloat16* Yl,
                               int M, int N, int K)
{
    dim3 grid((N + 63) / 64, M / 128);
    gemm_mma<<<grid, 256, GSMEM>>>(Ah, Al, lda, Bh, Bl, bias, Yf, Yh, Yl, M, N, K);
}

extern "C" void kernel_launch(void* const* d_in, const int* in_sizes, int n_in,
                              void* d_out, int out_size)
{
    const float* tokens      = (const float*)d_in[0];
    const float* attn_norm_w = (const float*)d_in[1];
    const float* attn_wq     = (const float*)d_in[2];
    const float* attn_wkv    = (const float*)d_in[3];
    const float* attn_wo     = (const float*)d_in[4];
    const float* ff_norm_w   = (const float*)d_in[5];
    const float* ff_keys_w   = (const float*)d_in[6];
    const float* ff_keys_b   = (const float*)d_in[7];
    const float* ff_values_w = (const float*)d_in[8];
    const float* ff_values_b = (const float*)d_in[9];
    const float* res_norm_w  = (const float*)d_in[10];
    const float* res_wq      = (const float*)d_in[11];
    const float* res_wkv     = (const float*)d_in[12];
    const float* res_wo      = (const float*)d_in[13];
    float* out = (float*)d_out;

    cudaFuncSetAttribute(gemm_mma, cudaFuncAttributeMaxDynamicSharedMemorySize, GSMEM);

    float *B, *T, *KV, *kvm, *bias, *pacc, *pml;
    __nv_bfloat16 *XNh, *XNl, *XAh, *XAl, *ACTh, *ACTl, *RETh, *RETl, *XRh, *XRl, *Th, *Tl;
    __nv_bfloat16 *Wbigh, *Wbigl, *Wkvh, *Wkvl, *Rkvh, *Rkvl, *WoTh, *WoTl;
    __nv_bfloat16 *Wvph, *Wvpl, *Rwoh, *Rwol, *Cath, *Catl;
    cudaGetSymbolAddress((void**)&B,    g_B);
    cudaGetSymbolAddress((void**)&T,    g_T);
    cudaGetSymbolAddress((void**)&KV,   g_KV);
    cudaGetSymbolAddress((void**)&kvm,  g_kvm);
    cudaGetSymbolAddress((void**)&bias, g_bias);
    cudaGetSymbolAddress((void**)&pacc, g_pacc);
    cudaGetSymbolAddress((void**)&pml,  g_pml);
    cudaGetSymbolAddress((void**)&XNh,  g_XNh);  cudaGetSymbolAddress((void**)&XNl, g_XNl);
    cudaGetSymbolAddress((void**)&XAh,  g_XAh);  cudaGetSymbolAddress((void**)&XAl, g_XAl);
    cudaGetSymbolAddress((void**)&ACTh, g_ACTh); cudaGetSymbolAddress((void**)&ACTl, g_ACTl);
    cudaGetSymbolAddress((void**)&RETh, g_RETh); cudaGetSymbolAddress((void**)&RETl, g_RETl);
    cudaGetSymbolAddress((void**)&XRh,  g_XRh);  cudaGetSymbolAddress((void**)&XRl, g_XRl);
    cudaGetSymbolAddress((void**)&Th,   g_Th);   cudaGetSymbolAddress((void**)&Tl,  g_Tl);
    cudaGetSymbolAddress((void**)&Wbigh, g_Wbigh); cudaGetSymbolAddress((void**)&Wbigl, g_Wbigl);
    cudaGetSymbolAddress((void**)&Wkvh, g_Wkvh); cudaGetSymbolAddress((void**)&Wkvl, g_Wkvl);
    cudaGetSymbolAddress((void**)&Rkvh, g_Rkvh); cudaGetSymbolAddress((void**)&Rkvl, g_Rkvl);
    cudaGetSymbolAddress((void**)&WoTh, g_WoTh); cudaGetSymbolAddress((void**)&WoTl, g_WoTl);
    cudaGetSymbolAddress((void**)&Wvph, g_Wvph); cudaGetSymbolAddress((void**)&Wvpl, g_Wvpl);
    cudaGetSymbolAddress((void**)&Rwoh, g_Rwoh); cudaGetSymbolAddress((void**)&Rwol, g_Rwol);
    cudaGetSymbolAddress((void**)&Cath, g_Cath); cudaGetSymbolAddress((void**)&Catl, g_Catl);

    // ---- precompute: weights ----
    wbig_fill<<<(NBIG * 512 + 255) / 256, 256>>>(attn_wq, ff_keys_w, res_wq,
                                                 attn_norm_w, ff_norm_w, res_norm_w,
                                                 Wbigh, Wbigl);
    bias_fill<<<(NBIG + 255) / 256, 256>>>(ff_keys_b, bias);
    convw_kernel<<<(1024 * 512 + 255) / 256, 256>>>(attn_wkv, Wkvh, Wkvl, 1024 * 512);
    convw_kernel<<<(1024 * 512 + 255) / 256, 256>>>(res_wkv,  Rkvh, Rkvl, 1024 * 512);
    convw_kernel<<<(512 * 512 + 255) / 256, 256>>>(res_wo,   Rwoh, Rwol, 512 * 512);
    transw_kernel<<<(512 * 512 + 255) / 256, 256>>>(attn_wo, WoTh, WoTl);
    convw_pad_kernel<<<(DIM * DFFP + 255) / 256, 256>>>(ff_values_w, Wvph, Wvpl);

    // C_att = res_wkv @ attn_wo
    launch_gemm(Rkvh, Rkvl, 512, WoTh, WoTl, nullptr,
                nullptr, Cath, Catl, 1024, 512, 512);

    // tokens -> compressed T; tokens-kv slab (512 rows)
    init_tok<<<(CROWS * DIM + 255) / 256, 256>>>(tokens, T, Th, Tl);
    launch_gemm(Th, Tl, 512, Rkvh, Rkvl, nullptr,
                kvm, nullptr, nullptr, 512, 1024, 512);

    for (int e = 0; e < 3; e++) {
        const int Mr = (e == 0) ? 512 : 1024;     // e0 is g-degenerate
        const int nb = Mr >> 8;
        float* kv_att = kvm + 524288 + (size_t)(e * 2 + 0) * 1048576;
        float* kv_ret = kvm + 524288 + (size_t)(e * 2 + 1) * 1048576;

        rmsnorm_now<<<Mr / 8, 256>>>(T, XNh, XNl, Mr);

        // mega-GEMM: [Q | H | Qres]
        launch_gemm(XNh, XNl, 512, Wbigh, Wbigl, bias,
                    B, nullptr, nullptr, Mr, NBIG, 512);

        // self-attention (j-split x4 + combine)
        launch_gemm(Th, Tl, 512, Wkvh, Wkvl, nullptr,
                    KV, nullptr, nullptr, Mr, 1024, 512);
        self_attn_part<<<dim3(HEADS, nb, 4), 256>>>(B, NBIG, KV, pacc, pml, nb);
        self_attn_combine<<<nb * 8, 256>>>(pacc, pml, XAh, XAl, nb);

        // attended kv directly (WO folded): kv_att = XA @ C_att^T
        launch_gemm(XAh, XAl, 512, Cath, Catl, nullptr,
                    kv_att, nullptr, nullptr, Mr, 1024, 512);

        // feedforward
        geglu_split<<<(Mr * DFFP + 255) / 256, 256>>>(B, ACTh, ACTl, Mr * DFFP);
        launch_gemm(ACTh, ACTl, DFFP, Wvph, Wvpl, ff_values_b,
                    nullptr, RETh, RETl, Mr, 512, DFFP);
        launch_gemm(RETh, RETl, 512, Rkvh, Rkvl, nullptr,
                    kv_ret, nullptr, nullptr, Mr, 1024, 512);

        // residual pooled attention over unique messages
        res_attn_kernel<<<CROWS, 256>>>(B + QRES_OFF, NBIG, (e == 0) ? 511 : 1023,
                                        kvm, 3 + 4 * e, XRh, XRl);
        launch_gemm(XRh, XRl, 512, Rwoh, Rwol, nullptr,
                    T, Th, Tl, CROWS, 512, 512);
    }

    expand_kernel<<<(3072 * 512 + 255) / 256, 256>>>(T, out);
}

// round 8
// speedup vs baseline: 4.3995x; 1.0077x over previous
#include <cuda_runtime.h>
#include <cuda_bf16.h>
#include <math.h>
#include <stdint.h>

#define DIM     512
#define HEADS   8
#define DFF     1365
#define DFF2    2730
#define DFFP    1408            // DFF padded (K multiple of 32)
#define CROWS   1024            // compressed rows: (g,b,n)
#define NBIG    3756            // 512 + 2730 + 512 + 2 align pad
#define QRES_OFF 3242           // 512 + 2730
#define RMS_EPS 1.1920929e-07f

// ---------------- scratch (device globals) ----------------
static __device__ float g_B   [CROWS * NBIG];     // [Q | H | Qres]
static __device__ float g_T   [CROWS * DIM];
static __device__ float g_KV  [CROWS * 1024];
static __device__ float g_kvm [512 * 1024 + 6 * 1024 * 1024]; // tok + (att,ret)x3
static __device__ float g_bias[NBIG];
static __device__ float g_pacc[128 * 64 * 256];   // attention partials
static __device__ float g_pml [128 * 2 * 256];

static __device__ __nv_bfloat16 g_XNh[CROWS * DIM],  g_XNl[CROWS * DIM];
static __device__ __nv_bfloat16 g_XAh[CROWS * DIM],  g_XAl[CROWS * DIM];
static __device__ __nv_bfloat16 g_ACTh[CROWS * DFFP], g_ACTl[CROWS * DFFP];
static __device__ __nv_bfloat16 g_RETh[CROWS * DIM], g_RETl[CROWS * DIM];
static __device__ __nv_bfloat16 g_XRh[CROWS * DIM],  g_XRl[CROWS * DIM];
static __device__ __nv_bfloat16 g_Th [CROWS * DIM],  g_Tl [CROWS * DIM];

static __device__ __nv_bfloat16 g_Wbigh[NBIG * 512], g_Wbigl[NBIG * 512];
static __device__ __nv_bfloat16 g_Wkvh[1024 * 512],  g_Wkvl[1024 * 512];
static __device__ __nv_bfloat16 g_Rkvh[1024 * 512],  g_Rkvl[1024 * 512];
static __device__ __nv_bfloat16 g_WoTh[512 * 512],   g_WoTl[512 * 512];
static __device__ __nv_bfloat16 g_Wvph[512 * DFFP],  g_Wvpl[512 * DFFP];
static __device__ __nv_bfloat16 g_Rwoh[512 * 512],   g_Rwol[512 * 512];
static __device__ __nv_bfloat16 g_Cath[1024 * 512],  g_Catl[1024 * 512];

// ---------------- helpers ----------------
__device__ __forceinline__ void split_bf16(float v, __nv_bfloat16& h, __nv_bfloat16& l) {
    h = __float2bfloat16(v);
    l = __float2bfloat16(v - __bfloat162float(h));
}
__device__ __forceinline__ uint32_t smem_u32(const void* p) {
    uint32_t a;
    asm("{ .reg .u64 t; cvta.to.shared.u64 t, %1; cvt.u32.u64 %0, t; }" : "=r"(a) : "l"(p));
    return a;
}
__device__ __forceinline__ void cp16(uint32_t dst, const void* src, uint32_t sz) {
    asm volatile("cp.async.cg.shared.global [%0], [%1], 16, %2;"
                 :: "r"(dst), "l"(src), "r"(sz));
}
__device__ __forceinline__ void ldsm4(uint32_t& r0, uint32_t& r1, uint32_t& r2,
                                      uint32_t& r3, uint32_t addr) {
    asm volatile("ldmatrix.sync.aligned.m8n8.x4.shared.b16 {%0,%1,%2,%3}, [%4];"
                 : "=r"(r0), "=r"(r1), "=r"(r2), "=r"(r3) : "r"(addr));
}
__device__ __forceinline__ void mma16816(float* c, const uint32_t* a, const uint32_t* b) {
    asm volatile(
        "mma.sync.aligned.m16n8k16.row.col.f32.bf16.bf16.f32 "
        "{%0,%1,%2,%3}, {%4,%5,%6,%7}, {%8,%9}, {%0,%1,%2,%3};"
        : "+f"(c[0]), "+f"(c[1]), "+f"(c[2]), "+f"(c[3])
        : "r"(a[0]), "r"(a[1]), "r"(a[2]), "r"(a[3]), "r"(b[0]), "r"(b[1]));
}

// ---------------- tensor-core split-bf16 GEMM, 3-stage cp.async pipeline --------
// BM=128, BN=64, BK=32; stage = 384 rows x 80B = 30720B; 3 stages = 92160B.
#define GSTAGE 30720
#define GSMEM  (3 * GSTAGE)

__device__ __forceinline__ void g_loads(
    uint32_t sb, int tid, int buf, int ck,
    const __nv_bfloat16* Ah, const __nv_bfloat16* Al, int lda,
    const __nv_bfloat16* Bh, const __nv_bfloat16* Bl,
    int K, int N, int bm0, int bn0)
{
    const uint32_t bufbase = sb + (uint32_t)buf * GSTAGE;
#pragma unroll
    for (int i = 0; i < 6; i++) {
        int c = tid + i * 256;
        int R = c >> 2;
        int q = c & 3;
        uint32_t dst = bufbase + (uint32_t)R * 80u + (uint32_t)q * 16u;
        const __nv_bfloat16* src;
        uint32_t sz = 16;
        if (R < 256) {
            src = (R < 128 ? Ah : Al) + (size_t)(bm0 + (R & 127)) * lda;
        } else {
            int rg = bn0 + (R & 63);
            if (rg >= N) { rg = 0; sz = 0; }
            src = (R < 320 ? Bh : Bl) + (size_t)rg * K;
        }
        cp16(dst, src + ck * 32 + q * 8, sz);
    }
    asm volatile("cp.async.commit_group;");
}

__global__ __launch_bounds__(256) void gemm_mma(
    const __nv_bfloat16* __restrict__ Ah, const __nv_bfloat16* __restrict__ Al, int lda,
    const __nv_bfloat16* __restrict__ Bh, const __nv_bfloat16* __restrict__ Bl,
    const float* __restrict__ bias,
    float* __restrict__ Yf,
    __nv_bfloat16* __restrict__ Yh, __nv_bfloat16* __restrict__ Yl,
    int M, int N, int K)
{
    extern __shared__ __align__(16) char smem[];
    const uint32_t sb = smem_u32(smem);
    const int tid  = threadIdx.x;
    const int wid  = tid >> 5;
    const int lane = tid & 31;
    const int bn0  = blockIdx.x * 64;
    const int bm0  = blockIdx.y * 128;
    const int m0w  = (wid & 3) * 32;
    const int n0w  = (wid >> 2) * 32;

    float C[2][4][4];
#pragma unroll
    for (int mt = 0; mt < 2; mt++)
#pragma unroll
        for (int nt = 0; nt < 4; nt++)
#pragma unroll
            for (int v = 0; v < 4; v++) C[mt][nt][v] = 0.f;

    uint32_t aoffH[2], aoffL[2], boffH[2], boffL[2];
#pragma unroll
    for (int mt = 0; mt < 2; mt++) {
        uint32_t row = (uint32_t)(m0w + mt * 16 + (lane & 15));
        uint32_t kb  = (uint32_t)((lane >> 4) * 16);
        aoffH[mt] = sb + row * 80u + kb;
        aoffL[mt] = aoffH[mt] + 10240u;
    }
#pragma unroll
    for (int bt = 0; bt < 2; bt++) {
        uint32_t row = (uint32_t)(n0w + bt * 16 + (lane & 7) + ((lane >> 4) << 3));
        uint32_t kb  = (uint32_t)(((lane >> 3) & 1) * 16);
        boffH[bt] = sb + 20480u + row * 80u + kb;
        boffL[bt] = boffH[bt] + 5120u;
    }

    const int nk = K >> 5;
    g_loads(sb, tid, 0, 0, Ah, Al, lda, Bh, Bl, K, N, bm0, bn0);
    g_loads(sb, tid, 1, 1, Ah, Al, lda, Bh, Bl, K, N, bm0, bn0);

    int buf = 0;
    for (int t = 0; t < nk; t++) {
        if (t < nk - 1) asm volatile("cp.async.wait_group 1;" ::: "memory");
        else            asm volatile("cp.async.wait_group 0;" ::: "memory");
        __syncthreads();

        if (t + 2 < nk) {
            int lb = buf + 2; if (lb >= 3) lb -= 3;
            g_loads(sb, tid, lb, t + 2, Ah, Al, lda, Bh, Bl, K, N, bm0, bn0);
        }

        const uint32_t bofs = (uint32_t)buf * GSTAGE;
#pragma unroll
        for (int ks = 0; ks < 2; ks++) {
            const uint32_t ko = bofs + (uint32_t)ks * 32u;
            uint32_t ah[2][4], al[2][4], bh[4][2], bl[4][2];
#pragma unroll
            for (int mt = 0; mt < 2; mt++) {
                ldsm4(ah[mt][0], ah[mt][1], ah[mt][2], ah[mt][3], aoffH[mt] + ko);
                ldsm4(al[mt][0], al[mt][1], al[mt][2], al[mt][3], aoffL[mt] + ko);
            }
            ldsm4(bh[0][0], bh[0][1], bh[1][0], bh[1][1], boffH[0] + ko);
            ldsm4(bh[2][0], bh[2][1], bh[3][0], bh[3][1], boffH[1] + ko);
            ldsm4(bl[0][0], bl[0][1], bl[1][0], bl[1][1], boffL[0] + ko);
            ldsm4(bl[2][0], bl[2][1], bl[3][0], bl[3][1], boffL[1] + ko);
#pragma unroll
            for (int mt = 0; mt < 2; mt++)
#pragma unroll
                for (int nt = 0; nt < 4; nt++) {
                    mma16816(C[mt][nt], ah[mt], bh[nt]);
                    mma16816(C[mt][nt], ah[mt], bl[nt]);
                    mma16816(C[mt][nt], al[mt], bh[nt]);
                }
        }
        buf = (buf == 2) ? 0 : buf + 1;
    }

#pragma unroll
    for (int mt = 0; mt < 2; mt++) {
        const int row = bm0 + m0w + mt * 16 + (lane >> 2);
#pragma unroll
        for (int nt = 0; nt < 4; nt++) {
            const int col = bn0 + n0w + nt * 8 + (lane & 3) * 2;
            if (col < N) {
                float b0 = bias ? bias[col]     : 0.f;
                float b1 = bias ? bias[col + 1] : 0.f;
                float v00 = C[mt][nt][0] + b0, v01 = C[mt][nt][1] + b1;
                float v10 = C[mt][nt][2] + b0, v11 = C[mt][nt][3] + b1;
                const size_t o0 = (size_t)row * N + col;
                const size_t o1 = (size_t)(row + 8) * N + col;
                if (Yf) {
                    *reinterpret_cast<float2*>(Yf + o0) = make_float2(v00, v01);
                    *reinterpret_cast<float2*>(Yf + o1) = make_float2(v10, v11);
                }
                if (Yh) {
                    __nv_bfloat16 h0, l0, h1, l1;
                    split_bf16(v00, h0, l0); split_bf16(v01, h1, l1);
                    *reinterpret_cast<__nv_bfloat162*>(Yh + o0) = __nv_bfloat162(h0, h1);
                    *reinterpret_cast<__nv_bfloat162*>(Yl + o0) = __nv_bfloat162(l0, l1);
                    split_bf16(v10, h0, l0); split_bf16(v11, h1, l1);
                    *reinterpret_cast<__nv_bfloat162*>(Yh + o1) = __nv_bfloat162(h0, h1);
                    *reinterpret_cast<__nv_bfloat162*>(Yl + o1) = __nv_bfloat162(l0, l1);
                }
            }
        }
    }
}

// ---------------- packed f32x2 helpers ----------------
__device__ __forceinline__ void ffma2(unsigned long long& d, unsigned long long a,
                                      unsigned long long b) {
    asm("fma.rn.f32x2 %0, %1, %2, %0;" : "+l"(d) : "l"(a), "l"(b));
}
__device__ __forceinline__ unsigned long long fma2_3(unsigned long long a,
                                                     unsigned long long b,
                                                     unsigned long long c) {
    unsigned long long d;
    asm("fma.rn.f32x2 %0, %1, %2, %3;" : "=l"(d) : "l"(a), "l"(b), "l"(c));
    return d;
}
__device__ __forceinline__ unsigned long long mul2(unsigned long long a,
                                                   unsigned long long b) {
    unsigned long long d;
    asm("mul.rn.f32x2 %0, %1, %2;" : "=l"(d) : "l"(a), "l"(b));
    return d;
}
__device__ __forceinline__ unsigned long long dup2(float x) {
    unsigned long long r;
    asm("mov.b64 %0, {%1, %1};" : "=l"(r) : "f"(x));
    return r;
}
__device__ __forceinline__ unsigned long long pk2(float x, float y) {
    unsigned long long r;
    asm("mov.b64 %0, {%1, %2};" : "=l"(r) : "f"(x), "f"(y));
    return r;
}
__device__ __forceinline__ float2 unpack2(unsigned long long v) {
    float2 f;
    asm("mov.b64 {%0, %1}, %2;" : "=f"(f.x), "=f"(f.y) : "l"(v));
    return f;
}

// ---------------- RMSNorm (weight folded into GEMM weights) ----------------
__global__ __launch_bounds__(256) void rmsnorm_now(
    const float* __restrict__ X,
    __nv_bfloat16* __restrict__ Yh, __nv_bfloat16* __restrict__ Yl, int rows)
{
    int row  = blockIdx.x * 8 + (threadIdx.x >> 5);
    int lane = threadIdx.x & 31;
    if (row >= rows) return;
    const float* xp = X + (size_t)row * DIM;
    float x[16];
    float ss = 0.f;
#pragma unroll
    for (int t = 0; t < 16; t++) { x[t] = xp[lane + t * 32]; ss += x[t] * x[t]; }
#pragma unroll
    for (int o = 16; o > 0; o >>= 1) ss += __shfl_xor_sync(0xffffffffu, ss, o);
    float rs = rsqrtf(ss * (1.0f / 512.0f) + RMS_EPS);
#pragma unroll
    for (int t = 0; t < 16; t++) {
        int c = lane + t * 32;
        __nv_bfloat16 h, l;
        split_bf16(x[t] * rs, h, l);
        Yh[(size_t)row * DIM + c] = h;
        Yl[(size_t)row * DIM + c] = l;
    }
}

// ---------------- Self attention, split over 4 key-chunks ----------------
__global__ __launch_bounds__(256) void self_attn_part(
    const float* __restrict__ Q, int ldq, const float* __restrict__ KV,
    float* __restrict__ pacc, float* __restrict__ pml, int nbatch)
{
    const int h     = blockIdx.x;
    const int batch = blockIdx.y;
    const int jc    = blockIdx.z;
    const int i     = threadIdx.x;
    const int j0    = jc * 64;

    __shared__ __align__(16) float Ks[64][64];
    __shared__ __align__(16) float Vs[64][64];

    unsigned long long qp[32];
    {
        const float4* qq = reinterpret_cast<const float4*>(
            Q + ((size_t)(batch * 256 + i)) * ldq + h * 64);
#pragma unroll
        for (int t = 0; t < 16; t++) {
            float4 v = qq[t];
            qp[2 * t]     = pk2(v.x, v.y);
            qp[2 * t + 1] = pk2(v.z, v.w);
        }
    }

#pragma unroll
    for (int s = 0; s < 4; s++) {
        int u  = threadIdx.x + s * 256;
        int jr = u >> 4;
        int c4 = u & 15;
        const float* kp = KV + ((size_t)(batch * 256 + j0 + jr)) * 1024 + h * 64 + c4 * 4;
        *reinterpret_cast<float4*>(&Ks[jr][c4 * 4]) = *reinterpret_cast<const float4*>(kp);
        *reinterpret_cast<float4*>(&Vs[jr][c4 * 4]) = *reinterpret_cast<const float4*>(kp + 512);
    }
    __syncthreads();

    float m = -1e30f, l = 0.f;
    unsigned long long acc[32];
#pragma unroll
    for (int t = 0; t < 32; t++) acc[t] = 0ull;

    for (int j = 0; j < 64; j++) {
        const ulonglong2* kr = reinterpret_cast<const ulonglong2*>(Ks[j]);
        unsigned long long s0 = 0ull, s1 = 0ull;
#pragma unroll
        for (int t = 0; t < 8; t++) {
            ulonglong2 k0 = kr[2 * t];
            ulonglong2 k1 = kr[2 * t + 1];
            ffma2(s0, qp[4 * t + 0], k0.x);
            ffma2(s1, qp[4 * t + 1], k0.y);
            ffma2(s0, qp[4 * t + 2], k1.x);
            ffma2(s1, qp[4 * t + 3], k1.y);
        }
        float2 sa = unpack2(s0), sb = unpack2(s1);
        float s = (sa.x + sa.y) + (sb.x + sb.y);

        float mn = fmaxf(m, s);
        float f  = __expf(m - mn);
        float p  = __expf(s - mn);
        l = l * f + p;
        unsigned long long fd = dup2(f), pd = dup2(p);
        const ulonglong2* vr = reinterpret_cast<const ulonglong2*>(Vs[j]);
#pragma unroll
        for (int t = 0; t < 16; t++) {
            ulonglong2 vv = vr[t];
            acc[2 * t]     = fma2_3(acc[2 * t],     fd, mul2(vv.x, pd));
            acc[2 * t + 1] = fma2_3(acc[2 * t + 1], fd, mul2(vv.y, pd));
        }
        m = mn;
    }

    const int bl = (jc * nbatch + batch) * HEADS + h;
    float* pa = pacc + ((size_t)bl * 64) * 256;
#pragma unroll
    for (int t = 0; t < 32; t++) {
        float2 a = unpack2(acc[t]);
        pa[(2 * t) * 256 + i]     = a.x;
        pa[(2 * t + 1) * 256 + i] = a.y;
    }
    pml[(bl * 2 + 0) * 256 + i] = m;
    pml[(bl * 2 + 1) * 256 + i] = l;
}

__global__ __launch_bounds__(256) void self_attn_combine(
    const float* __restrict__ pacc, const float* __restrict__ pml,
    __nv_bfloat16* __restrict__ Oh, __nv_bfloat16* __restrict__ Ol, int nbatch)
{
    int idx   = blockIdx.x * 256 + threadIdx.x;
    int i     = idx & 255;
    int h     = (idx >> 8) & 7;
    int batch = idx >> 11;

    float mc[4], lc[4];
    float M = -1e30f;
#pragma unroll
    for (int c = 0; c < 4; c++) {
        int bl = (c * nbatch + batch) * HEADS + h;
        mc[c] = pml[(bl * 2 + 0) * 256 + i];
        lc[c] = pml[(bl * 2 + 1) * 256 + i];
        M = fmaxf(M, mc[c]);
    }
    float w[4];
    float L = 0.f;
#pragma unroll
    for (int c = 0; c < 4; c++) { w[c] = __expf(mc[c] - M); L += lc[c] * w[c]; }
    float inv = 1.0f / L;

    size_t ob = ((size_t)(batch * 256 + i)) * 512 + h * 64;
#pragma unroll
    for (int t = 0; t < 64; t++) {
        float o = 0.f;
#pragma unroll
        for (int c = 0; c < 4; c++) {
            int bl = (c * nbatch + batch) * HEADS + h;
            o += w[c] * pacc[((size_t)bl * 64 + t) * 256 + i];
        }
        __nv_bfloat16 hh, ll;
        split_bf16(o * inv, hh, ll);
        Oh[ob + t] = hh;
        Ol[ob + t] = ll;
    }
}

// ---------------- Residual attention over unique messages ----------------
__device__ __forceinline__ const float* msg_ptr(
    const float* KVM, int u, int g, int n, float* w)
{
    if (u == 0) { *w = 6.f; return KVM + ((size_t)(g * 256 + n)) * 1024; }
    if (u <= 2) { *w = 6.f;
        return KVM + 524288u + (size_t)(u - 1) * 1048576u + ((size_t)(g * 256 + n)) * 1024; }
    int j = 1 + ((u - 3) >> 2), t = (u - 3) & 3;
    int type = t >> 1, gpp = t & 1;
    *w = 3.f;
    return KVM + 524288u + ((size_t)(j * 2 + type)) * 1048576u
         + ((size_t)((gpp * 2 + g) * 256 + n)) * 1024;
}

__global__ __launch_bounds__(256) void res_attn_kernel(
    const float* __restrict__ Qr, int ldq, int qmask,
    const float* __restrict__ KVM, int Mu,
    __nv_bfloat16* __restrict__ Oh, __nv_bfloat16* __restrict__ Ol)
{
    const int r = blockIdx.x;
    const int g = r >> 9;
    const int n = r & 255;
    const int qrow = r & qmask;

    const int tid  = threadIdx.x;
    const int h    = tid >> 5;
    const int lane = tid & 31;

    __shared__ float qs[512];
    __shared__ float sim[8][16];

    qs[tid]       = Qr[(size_t)qrow * ldq + tid];
    qs[tid + 256] = Qr[(size_t)qrow * ldq + tid + 256];
    __syncthreads();

    float sc = -1e30f;
    float wl = 0.f;
    if (lane < Mu) {
        const float* kpl = msg_ptr(KVM, lane, g, n, &wl);
        const float4* k4 = reinterpret_cast<const float4*>(kpl + h * 64);
        const float4* q4 = reinterpret_cast<const float4*>(&qs[h * 64]);
        float s = 0.f;
#pragma unroll
        for (int t = 0; t < 16; t++) {
            float4 kk = k4[t];
            float4 qq = q4[t];
            s += qq.x * kk.x + qq.y * kk.y + qq.z * kk.z + qq.w * kk.w;
        }
        sc = s;
    }
    float mx = sc;
#pragma unroll
    for (int o = 16; o > 0; o >>= 1) mx = fmaxf(mx, __shfl_xor_sync(0xffffffffu, mx, o));
    float p = (lane < Mu) ? wl * __expf(sc - mx) : 0.f;
    if (lane < 16) sim[h][lane] = p;
    float ls = p;
#pragma unroll
    for (int o = 16; o > 0; o >>= 1) ls += __shfl_xor_sync(0xffffffffu, ls, o);
    __syncwarp();

    float o0 = 0.f, o1 = 0.f;
    for (int u = 0; u < Mu; u++) {
        float a = sim[h][u];
        float dummy;
        const float* vp = msg_ptr(KVM, u, g, n, &dummy) + 512;
        o0 += a * vp[h * 64 + lane];
        o1 += a * vp[h * 64 + lane + 32];
    }
    float inv = 1.0f / ls;
    __nv_bfloat16 hh, ll;
    split_bf16(o0 * inv, hh, ll);
    Oh[(size_t)r * 512 + h * 64 + lane] = hh;
    Ol[(size_t)r * 512 + h * 64 + lane] = ll;
    split_bf16(o1 * inv, hh, ll);
    Oh[(size_t)r * 512 + h * 64 + lane + 32] = hh;
    Ol[(size_t)r * 512 + h * 64 + lane + 32] = ll;
}

// ---------------- GEGLU from g_B (stride NBIG) -> split ACT ----------------
__global__ void geglu_split(const float* __restrict__ B,
                            __nv_bfloat16* __restrict__ Ah,
                            __nv_bfloat16* __restrict__ Al, int count)
{
    int idx = blockIdx.x * blockDim.x + threadIdx.x;
    if (idx >= count) return;
    int row = idx / DFFP;
    int e   = idx - row * DFFP;
    float out = 0.f;
    if (e < DFF) {
        float s = B[(size_t)row * NBIG + 512 + e];
        float gg = B[(size_t)row * NBIG + 512 + DFF + e];
        out = s * (0.5f * gg * (1.0f + erff(gg * 0.70710678118654752440f)));
    }
    __nv_bfloat16 h, l;
    split_bf16(out, h, l);
    Ah[idx] = h;
    Al[idx] = l;
}

// ---------------- init: tokens -> compressed T (dup over g) ----------------
__global__ void init_tok(const float* __restrict__ tokens,
                         float* __restrict__ T,
                         __nv_bfloat16* __restrict__ Th, __nv_bfloat16* __restrict__ Tl)
{
    int idx = blockIdx.x * blockDim.x + threadIdx.x;
    if (idx >= CROWS * DIM) return;
    int d = idx & 511;
    int r = idx >> 9;
    int n = r & 255;
    int b = (r >> 8) & 1;
    float v = tokens[((size_t)(b * 256 + n)) * 512 + d];
    T[idx] = v;
    __nv_bfloat16 h, l;
    split_bf16(v, h, l);
    Th[idx] = h; Tl[idx] = l;
}

// ---------------- fused weight preparation (single launch) ----------------
#define SEG0 1923072               // wbig: NBIG*512
#define SEG1 (SEG0 + 524288)       // wkv
#define SEG2 (SEG1 + 524288)       // rkv
#define SEG3 (SEG2 + 262144)       // rwo
#define SEG4 (SEG3 + 262144)       // woT
#define SEG5 (SEG4 + 720896)       // wvp: 512*1408
#define SEG6 (SEG5 + NBIG)         // bias
__global__ void prep_all(
    const float* __restrict__ wq, const float* __restrict__ ffk,
    const float* __restrict__ rq,
    const float* __restrict__ anw, const float* __restrict__ fnw,
    const float* __restrict__ rnw,
    const float* __restrict__ wkv, const float* __restrict__ rkv,
    const float* __restrict__ rwo, const float* __restrict__ wo,
    const float* __restrict__ wvals, const float* __restrict__ ffb,
    __nv_bfloat16* __restrict__ Wbigh, __nv_bfloat16* __restrict__ Wbigl,
    __nv_bfloat16* __restrict__ Wkvh,  __nv_bfloat16* __restrict__ Wkvl,
    __nv_bfloat16* __restrict__ Rkvh,  __nv_bfloat16* __restrict__ Rkvl,
    __nv_bfloat16* __restrict__ Rwoh,  __nv_bfloat16* __restrict__ Rwol,
    __nv_bfloat16* __restrict__ WoTh,  __nv_bfloat16* __restrict__ WoTl,
    __nv_bfloat16* __restrict__ Wvph,  __nv_bfloat16* __restrict__ Wvpl,
    float* __restrict__ bias)
{
    int idx = blockIdx.x * 256 + threadIdx.x;
    if (idx >= SEG6) return;
    __nv_bfloat16 h, l;
    if (idx < SEG0) {
        int row = idx >> 9, k = idx & 511;
        float v = 0.f;
        if (row < 512)            v = wq [(size_t)row * 512 + k] * anw[k];
        else if (row < QRES_OFF)  v = ffk[(size_t)(row - 512) * 512 + k] * fnw[k];
        else if (row < 3754)      v = rq [(size_t)(row - QRES_OFF) * 512 + k] * rnw[k];
        split_bf16(v, h, l);
        Wbigh[idx] = h; Wbigl[idx] = l;
    } else if (idx < SEG1) {
        int i = idx - SEG0;
        split_bf16(wkv[i], h, l);
        Wkvh[i] = h; Wkvl[i] = l;
    } else if (idx < SEG2) {
        int i = idx - SEG1;
        split_bf16(rkv[i], h, l);
        Rkvh[i] = h; Rkvl[i] = l;
    } else if (idx < SEG3) {
        int i = idx - SEG2;
        split_bf16(rwo[i], h, l);
        Rwoh[i] = h; Rwol[i] = l;
    } else if (idx < SEG4) {
        int i = idx - SEG3;
        int e = i >> 9, d = i & 511;
        split_bf16(wo[(size_t)d * 512 + e], h, l);
        WoTh[i] = h; WoTl[i] = l;
    } else if (idx < SEG5) {
        int i = idx - SEG4;
        int row = i / DFFP, col = i - row * DFFP;
        float v = (col < DFF) ? wvals[(size_t)row * DFF + col] : 0.f;
        split_bf16(v, h, l);
        Wvph[i] = h; Wvpl[i] = l;
    } else {
        int i = idx - SEG5;
        bias[i] = (i >= 512 && i < QRES_OFF) ? ffb[i - 512] : 0.f;
    }
}

// ---------------- expand compressed T -> output (3072 rows) ----------------
__global__ void expand_kernel(const float* __restrict__ T, float* __restrict__ out)
{
    int idx = blockIdx.x * blockDim.x + threadIdx.x;
    if (idx >= 3072 * 512) return;
    int d  = idx & 511;
    int r2 = idx >> 9;
    int n  = r2 & 255;
    int b  = (r2 >> 8) & 1;
    int block = r2 >> 9;
    int g = (2 * block + b) / 6;
    out[idx] = T[((size_t)((g * 2 + b) * 256 + n)) * 512 + d];
}

// -------------------------------- launch --------------------------------------
static inline void launch_gemm(const __nv_bfloat16* Ah, const __nv_bfloat16* Al, int lda,
                               const __nv_bfloat16* Bh, const __nv_bfloat16* Bl,
                               const float* bias, float* Yf,
                               __nv_bfloat16* Yh, __nv_bfloat16* Yl,
                               int M, int N, int K)
{
    dim3 grid((N + 63) / 64, M / 128);
    gemm_mma<<<grid, 256, GSMEM>>>(Ah, Al, lda, Bh, Bl, bias, Yf, Yh, Yl, M, N, K);
}

extern "C" void kernel_launch(void* const* d_in, const int* in_sizes, int n_in,
                              void* d_out, int out_size)
{
    const float* tokens      = (const float*)d_in[0];
    const float* attn_norm_w = (const float*)d_in[1];
    const float* attn_wq     = (const float*)d_in[2];
    const float* attn_wkv    = (const float*)d_in[3];
    const float* attn_wo     = (const float*)d_in[4];
    const float* ff_norm_w   = (const float*)d_in[5];
    const float* ff_keys_w   = (const float*)d_in[6];
    const float* ff_keys_b   = (const float*)d_in[7];
    const float* ff_values_w = (const float*)d_in[8];
    const float* ff_values_b = (const float*)d_in[9];
    const float* res_norm_w  = (const float*)d_in[10];
    const float* res_wq      = (const float*)d_in[11];
    const float* res_wkv     = (const float*)d_in[12];
    const float* res_wo      = (const float*)d_in[13];
    float* out = (float*)d_out;

    cudaFuncSetAttribute(gemm_mma, cudaFuncAttributeMaxDynamicSharedMemorySize, GSMEM);

    float *B, *T, *KV, *kvm, *bias, *pacc, *pml;
    __nv_bfloat16 *XNh, *XNl, *XAh, *XAl, *ACTh, *ACTl, *RETh, *RETl, *XRh, *XRl, *Th, *Tl;
    __nv_bfloat16 *Wbigh, *Wbigl, *Wkvh, *Wkvl, *Rkvh, *Rkvl, *WoTh, *WoTl;
    __nv_bfloat16 *Wvph, *Wvpl, *Rwoh, *Rwol, *Cath, *Catl;
    cudaGetSymbolAddress((void**)&B,    g_B);
    cudaGetSymbolAddress((void**)&T,    g_T);
    cudaGetSymbolAddress((void**)&KV,   g_KV);
    cudaGetSymbolAddress((void**)&kvm,  g_kvm);
    cudaGetSymbolAddress((void**)&bias, g_bias);
    cudaGetSymbolAddress((void**)&pacc, g_pacc);
    cudaGetSymbolAddress((void**)&pml,  g_pml);
    cudaGetSymbolAddress((void**)&XNh,  g_XNh);  cudaGetSymbolAddress((void**)&XNl, g_XNl);
    cudaGetSymbolAddress((void**)&XAh,  g_XAh);  cudaGetSymbolAddress((void**)&XAl, g_XAl);
    cudaGetSymbolAddress((void**)&ACTh, g_ACTh); cudaGetSymbolAddress((void**)&ACTl, g_ACTl);
    cudaGetSymbolAddress((void**)&RETh, g_RETh); cudaGetSymbolAddress((void**)&RETl, g_RETl);
    cudaGetSymbolAddress((void**)&XRh,  g_XRh);  cudaGetSymbolAddress((void**)&XRl, g_XRl);
    cudaGetSymbolAddress((void**)&Th,   g_Th);   cudaGetSymbolAddress((void**)&Tl,  g_Tl);
    cudaGetSymbolAddress((void**)&Wbigh, g_Wbigh); cudaGetSymbolAddress((void**)&Wbigl, g_Wbigl);
    cudaGetSymbolAddress((void**)&Wkvh, g_Wkvh); cudaGetSymbolAddress((void**)&Wkvl, g_Wkvl);
    cudaGetSymbolAddress((void**)&Rkvh, g_Rkvh); cudaGetSymbolAddress((void**)&Rkvl, g_Rkvl);
    cudaGetSymbolAddress((void**)&WoTh, g_WoTh); cudaGetSymbolAddress((void**)&WoTl, g_WoTl);
    cudaGetSymbolAddress((void**)&Wvph, g_Wvph); cudaGetSymbolAddress((void**)&Wvpl, g_Wvpl);
    cudaGetSymbolAddress((void**)&Rwoh, g_Rwoh); cudaGetSymbolAddress((void**)&Rwol, g_Rwol);
    cudaGetSymbolAddress((void**)&Cath, g_Cath); cudaGetSymbolAddress((void**)&Catl, g_Catl);

    // launch #1: fused weight prep
    prep_all<<<(SEG6 + 255) / 256, 256>>>(
        attn_wq, ff_keys_w, res_wq, attn_norm_w, ff_norm_w, res_norm_w,
        attn_wkv, res_wkv, res_wo, attn_wo, ff_values_w, ff_keys_b,
        Wbigh, Wbigl, Wkvh, Wkvl, Rkvh, Rkvl, Rwoh, Rwol,
        WoTh, WoTl, Wvph, Wvpl, bias);

    // launch #2: C_att = res_wkv @ attn_wo
    launch_gemm(Rkvh, Rkvl, 512, WoTh, WoTl, nullptr,
                nullptr, Cath, Catl, 1024, 512, 512);

    // launch #3: tokens -> compressed T; launch #4: tokens-kv slab
    init_tok<<<(CROWS * DIM + 255) / 256, 256>>>(tokens, T, Th, Tl);
    launch_gemm(Th, Tl, 512, Rkvh, Rkvl, nullptr,
                kvm, nullptr, nullptr, 512, 1024, 512);

    for (int e = 0; e < 3; e++) {
        const int Mr = (e == 0) ? 512 : 1024;     // e0 is g-degenerate
        const int nb = Mr >> 8;
        float* kv_att = kvm + 524288 + (size_t)(e * 2 + 0) * 1048576;
        float* kv_ret = kvm + 524288 + (size_t)(e * 2 + 1) * 1048576;

        // launch #5 (e0): rmsnorm; launch #6 (e0): mega-GEMM (ncu capture target)
        rmsnorm_now<<<Mr / 8, 256>>>(T, XNh, XNl, Mr);
        launch_gemm(XNh, XNl, 512, Wbigh, Wbigl, bias,
                    B, nullptr, nullptr, Mr, NBIG, 512);

        // self-attention (j-split x4 + combine)
        launch_gemm(Th, Tl, 512, Wkvh, Wkvl, nullptr,
                    KV, nullptr, nullptr, Mr, 1024, 512);
        self_attn_part<<<dim3(HEADS, nb, 4), 256>>>(B, NBIG, KV, pacc, pml, nb);
        self_attn_combine<<<nb * 8, 256>>>(pacc, pml, XAh, XAl, nb);

        // attended kv directly (WO folded): kv_att = XA @ C_att^T
        launch_gemm(XAh, XAl, 512, Cath, Catl, nullptr,
                    kv_att, nullptr, nullptr, Mr, 1024, 512);

        // feedforward
        geglu_split<<<(Mr * DFFP + 255) / 256, 256>>>(B, ACTh, ACTl, Mr * DFFP);
        launch_gemm(ACTh, ACTl, DFFP, Wvph, Wvpl, ff_values_b,
                    nullptr, RETh, RETl, Mr, 512, DFFP);
        launch_gemm(RETh, RETl, 512, Rkvh, Rkvl, nullptr,
                    kv_ret, nullptr, nullptr, Mr, 1024, 512);

        // residual pooled attention over unique messages
        res_attn_kernel<<<CROWS, 256>>>(B + QRES_OFF, NBIG, (e == 0) ? 511 : 1023,
                                        kvm, 3 + 4 * e, XRh, XRl);
        launch_gemm(XRh, XRl, 512, Rwoh, Rwol, nullptr,
                    T, (e == 2) ? nullptr : Th, (e == 2) ? nullptr : Tl,
                    CROWS, 512, 512);
    }

    expand_kernel<<<(3072 * 512 + 255) / 256, 256>>>(T, out);
}

// round 9
// speedup vs baseline: 5.1039x; 1.1601x over previous
#include <cuda_runtime.h>
#include <cuda_bf16.h>
#include <math.h>
#include <stdint.h>

#define DIM     512
#define HEADS   8
#define DFF     1365
#define DFF2    2730
#define DFFP    1408            // DFF padded (K multiple of 32)
#define CROWS   1024            // compressed rows: (g,b,n)
#define NBIG    3756            // 512 + 2730 + 512 + 2 align pad
#define QRES_OFF 3242           // 512 + 2730
#define RMS_EPS 1.1920929e-07f

// ---------------- scratch (device globals) ----------------
static __device__ float g_B   [CROWS * NBIG];     // [Q | H | Qres]
static __device__ float g_T   [CROWS * DIM];
static __device__ float g_KV  [CROWS * 1024];
static __device__ float g_kvm [512 * 1024 + 6 * 1024 * 1024]; // tok + (att,ret)x3
static __device__ float g_bias[NBIG];
static __device__ float g_pacc[128 * 64 * 256];   // attention partials
static __device__ float g_pml [128 * 2 * 256];
static __device__ float g_part[1 << 21];          // split-K partials (8MB)

static __device__ __nv_bfloat16 g_XNh[CROWS * DIM],  g_XNl[CROWS * DIM];
static __device__ __nv_bfloat16 g_XAh[CROWS * DIM],  g_XAl[CROWS * DIM];
static __device__ __nv_bfloat16 g_ACTh[CROWS * DFFP], g_ACTl[CROWS * DFFP];
static __device__ __nv_bfloat16 g_RETh[CROWS * DIM], g_RETl[CROWS * DIM];
static __device__ __nv_bfloat16 g_XRh[CROWS * DIM],  g_XRl[CROWS * DIM];
static __device__ __nv_bfloat16 g_Th [CROWS * DIM],  g_Tl [CROWS * DIM];

static __device__ __nv_bfloat16 g_Wbigh[NBIG * 512], g_Wbigl[NBIG * 512];
static __device__ __nv_bfloat16 g_Wkvh[1024 * 512],  g_Wkvl[1024 * 512];
static __device__ __nv_bfloat16 g_Rkvh[1024 * 512],  g_Rkvl[1024 * 512];
static __device__ __nv_bfloat16 g_WoTh[512 * 512],   g_WoTl[512 * 512];
static __device__ __nv_bfloat16 g_Wvph[512 * DFFP],  g_Wvpl[512 * DFFP];
static __device__ __nv_bfloat16 g_Rwoh[512 * 512],   g_Rwol[512 * 512];
static __device__ __nv_bfloat16 g_Cath[1024 * 512],  g_Catl[1024 * 512];

// ---------------- helpers ----------------
__device__ __forceinline__ void split_bf16(float v, __nv_bfloat16& h, __nv_bfloat16& l) {
    h = __float2bfloat16(v);
    l = __float2bfloat16(v - __bfloat162float(h));
}
__device__ __forceinline__ uint32_t smem_u32(const void* p) {
    uint32_t a;
    asm("{ .reg .u64 t; cvta.to.shared.u64 t, %1; cvt.u32.u64 %0, t; }" : "=r"(a) : "l"(p));
    return a;
}
__device__ __forceinline__ void cp16(uint32_t dst, const void* src, uint32_t sz) {
    asm volatile("cp.async.cg.shared.global [%0], [%1], 16, %2;"
                 :: "r"(dst), "l"(src), "r"(sz));
}
__device__ __forceinline__ void ldsm4(uint32_t& r0, uint32_t& r1, uint32_t& r2,
                                      uint32_t& r3, uint32_t addr) {
    asm volatile("ldmatrix.sync.aligned.m8n8.x4.shared.b16 {%0,%1,%2,%3}, [%4];"
                 : "=r"(r0), "=r"(r1), "=r"(r2), "=r"(r3) : "r"(addr));
}
__device__ __forceinline__ void mma16816(float* c, const uint32_t* a, const uint32_t* b) {
    asm volatile(
        "mma.sync.aligned.m16n8k16.row.col.f32.bf16.bf16.f32 "
        "{%0,%1,%2,%3}, {%4,%5,%6,%7}, {%8,%9}, {%0,%1,%2,%3};"
        : "+f"(c[0]), "+f"(c[1]), "+f"(c[2]), "+f"(c[3])
        : "r"(a[0]), "r"(a[1]), "r"(a[2]), "r"(a[3]), "r"(b[0]), "r"(b[1]));
}

// ---------------- tensor-core split-bf16 GEMM, 3-stage pipeline + split-K -------
// BM=128, BN=64, BK=32; stage = 384 rows x 80B = 30720B; 3 stages = 92160B.
#define GSTAGE 30720
#define GSMEM  (3 * GSTAGE)

__device__ __forceinline__ void g_loads(
    uint32_t sb, int tid, int buf, int ck,
    const __nv_bfloat16* Ah, const __nv_bfloat16* Al, int lda,
    const __nv_bfloat16* Bh, const __nv_bfloat16* Bl,
    int K, int N, int bm0, int bn0)
{
    const uint32_t bufbase = sb + (uint32_t)buf * GSTAGE;
#pragma unroll
    for (int i = 0; i < 6; i++) {
        int c = tid + i * 256;
        int R = c >> 2;
        int q = c & 3;
        uint32_t dst = bufbase + (uint32_t)R * 80u + (uint32_t)q * 16u;
        const __nv_bfloat16* src;
        uint32_t sz = 16;
        if (R < 256) {
            src = (R < 128 ? Ah : Al) + (size_t)(bm0 + (R & 127)) * lda;
        } else {
            int rg = bn0 + (R & 63);
            if (rg >= N) { rg = 0; sz = 0; }
            src = (R < 320 ? Bh : Bl) + (size_t)rg * K;
        }
        cp16(dst, src + ck * 32 + q * 8, sz);
    }
    asm volatile("cp.async.commit_group;");
}

__global__ __launch_bounds__(256) void gemm_mma(
    const __nv_bfloat16* __restrict__ Ah, const __nv_bfloat16* __restrict__ Al, int lda,
    const __nv_bfloat16* __restrict__ Bh, const __nv_bfloat16* __restrict__ Bl,
    const float* __restrict__ bias,
    float* __restrict__ Yf,
    __nv_bfloat16* __restrict__ Yh, __nv_bfloat16* __restrict__ Yl,
    int M, int N, int K, int splitk, float* __restrict__ Pf)
{
    extern __shared__ __align__(16) char smem[];
    const uint32_t sb = smem_u32(smem);
    const int tid  = threadIdx.x;
    const int wid  = tid >> 5;
    const int lane = tid & 31;
    const int bn0  = blockIdx.x * 64;
    const int bm0  = blockIdx.y * 128;
    const int z    = blockIdx.z;
    const int m0w  = (wid & 3) * 32;
    const int n0w  = (wid >> 2) * 32;

    float C[2][4][4];
#pragma unroll
    for (int mt = 0; mt < 2; mt++)
#pragma unroll
        for (int nt = 0; nt < 4; nt++)
#pragma unroll
            for (int v = 0; v < 4; v++) C[mt][nt][v] = 0.f;

    uint32_t aoffH[2], aoffL[2], boffH[2], boffL[2];
#pragma unroll
    for (int mt = 0; mt < 2; mt++) {
        uint32_t row = (uint32_t)(m0w + mt * 16 + (lane & 15));
        uint32_t kb  = (uint32_t)((lane >> 4) * 16);
        aoffH[mt] = sb + row * 80u + kb;
        aoffL[mt] = aoffH[mt] + 10240u;
    }
#pragma unroll
    for (int bt = 0; bt < 2; bt++) {
        uint32_t row = (uint32_t)(n0w + bt * 16 + (lane & 7) + ((lane >> 4) << 3));
        uint32_t kb  = (uint32_t)(((lane >> 3) & 1) * 16);
        boffH[bt] = sb + 20480u + row * 80u + kb;
        boffL[bt] = boffH[bt] + 5120u;
    }

    const int kspan = K / splitk;
    const int nk    = kspan >> 5;
    const int kb32  = z * nk;
    g_loads(sb, tid, 0, kb32 + 0, Ah, Al, lda, Bh, Bl, K, N, bm0, bn0);
    g_loads(sb, tid, 1, kb32 + 1, Ah, Al, lda, Bh, Bl, K, N, bm0, bn0);

    int buf = 0;
    for (int t = 0; t < nk; t++) {
        if (t < nk - 1) asm volatile("cp.async.wait_group 1;" ::: "memory");
        else            asm volatile("cp.async.wait_group 0;" ::: "memory");
        __syncthreads();

        if (t + 2 < nk) {
            int lb = buf + 2; if (lb >= 3) lb -= 3;
            g_loads(sb, tid, lb, kb32 + t + 2, Ah, Al, lda, Bh, Bl, K, N, bm0, bn0);
        }

        const uint32_t bofs = (uint32_t)buf * GSTAGE;
#pragma unroll
        for (int ks = 0; ks < 2; ks++) {
            const uint32_t ko = bofs + (uint32_t)ks * 32u;
            uint32_t ah[2][4], al[2][4], bh[4][2], bl[4][2];
#pragma unroll
            for (int mt = 0; mt < 2; mt++) {
                ldsm4(ah[mt][0], ah[mt][1], ah[mt][2], ah[mt][3], aoffH[mt] + ko);
                ldsm4(al[mt][0], al[mt][1], al[mt][2], al[mt][3], aoffL[mt] + ko);
            }
            ldsm4(bh[0][0], bh[0][1], bh[1][0], bh[1][1], boffH[0] + ko);
            ldsm4(bh[2][0], bh[2][1], bh[3][0], bh[3][1], boffH[1] + ko);
            ldsm4(bl[0][0], bl[0][1], bl[1][0], bl[1][1], boffL[0] + ko);
            ldsm4(bl[2][0], bl[2][1], bl[3][0], bl[3][1], boffL[1] + ko);
#pragma unroll
            for (int mt = 0; mt < 2; mt++)
#pragma unroll
                for (int nt = 0; nt < 4; nt++) {
                    mma16816(C[mt][nt], ah[mt], bh[nt]);
                    mma16816(C[mt][nt], ah[mt], bl[nt]);
                    mma16816(C[mt][nt], al[mt], bh[nt]);
                }
        }
        buf = (buf == 2) ? 0 : buf + 1;
    }

    if (splitk > 1) {
        float* P = Pf + (size_t)z * M * N;
#pragma unroll
        for (int mt = 0; mt < 2; mt++) {
            const int row = bm0 + m0w + mt * 16 + (lane >> 2);
#pragma unroll
            for (int nt = 0; nt < 4; nt++) {
                const int col = bn0 + n0w + nt * 8 + (lane & 3) * 2;
                if (col < N) {
                    *reinterpret_cast<float2*>(P + (size_t)row * N + col)
                        = make_float2(C[mt][nt][0], C[mt][nt][1]);
                    *reinterpret_cast<float2*>(P + (size_t)(row + 8) * N + col)
                        = make_float2(C[mt][nt][2], C[mt][nt][3]);
                }
            }
        }
        return;
    }

#pragma unroll
    for (int mt = 0; mt < 2; mt++) {
        const int row = bm0 + m0w + mt * 16 + (lane >> 2);
#pragma unroll
        for (int nt = 0; nt < 4; nt++) {
            const int col = bn0 + n0w + nt * 8 + (lane & 3) * 2;
            if (col < N) {
                float b0 = bias ? bias[col]     : 0.f;
                float b1 = bias ? bias[col + 1] : 0.f;
                float v00 = C[mt][nt][0] + b0, v01 = C[mt][nt][1] + b1;
                float v10 = C[mt][nt][2] + b0, v11 = C[mt][nt][3] + b1;
                const size_t o0 = (size_t)row * N + col;
                const size_t o1 = (size_t)(row + 8) * N + col;
                if (Yf) {
                    *reinterpret_cast<float2*>(Yf + o0) = make_float2(v00, v01);
                    *reinterpret_cast<float2*>(Yf + o1) = make_float2(v10, v11);
                }
                if (Yh) {
                    __nv_bfloat16 h0, l0, h1, l1;
                    split_bf16(v00, h0, l0); split_bf16(v01, h1, l1);
                    *reinterpret_cast<__nv_bfloat162*>(Yh + o0) = __nv_bfloat162(h0, h1);
                    *reinterpret_cast<__nv_bfloat162*>(Yl + o0) = __nv_bfloat162(l0, l1);
                    split_bf16(v10, h0, l0); split_bf16(v11, h1, l1);
                    *reinterpret_cast<__nv_bfloat162*>(Yh + o1) = __nv_bfloat162(h0, h1);
                    *reinterpret_cast<__nv_bfloat162*>(Yl + o1) = __nv_bfloat162(l0, l1);
                }
            }
        }
    }
}

// ---------------- split-K combine: sum partials, +bias, emit outputs ------------
__global__ __launch_bounds__(256) void splitk_combine(
    const float* __restrict__ P, int parts, int MN, int N,
    const float* __restrict__ bias,
    float* __restrict__ Yf,
    __nv_bfloat16* __restrict__ Yh, __nv_bfloat16* __restrict__ Yl)
{
    int idx = (blockIdx.x * 256 + threadIdx.x) * 2;
    if (idx >= MN) return;
    float2 a = *reinterpret_cast<const float2*>(P + idx);
    for (int p = 1; p < parts; p++) {
        float2 b = *reinterpret_cast<const float2*>(P + (size_t)p * MN + idx);
        a.x += b.x; a.y += b.y;
    }
    if (bias) {
        int col = idx % N;
        a.x += bias[col];
        a.y += bias[col + 1];
    }
    if (Yf) *reinterpret_cast<float2*>(Yf + idx) = a;
    if (Yh) {
        __nv_bfloat16 h0, l0, h1, l1;
        split_bf16(a.x, h0, l0); split_bf16(a.y, h1, l1);
        *reinterpret_cast<__nv_bfloat162*>(Yh + idx) = __nv_bfloat162(h0, h1);
        *reinterpret_cast<__nv_bfloat162*>(Yl + idx) = __nv_bfloat162(l0, l1);
    }
}

// ---------------- packed f32x2 helpers ----------------
__device__ __forceinline__ void ffma2(unsigned long long& d, unsigned long long a,
                                      unsigned long long b) {
    asm("fma.rn.f32x2 %0, %1, %2, %0;" : "+l"(d) : "l"(a), "l"(b));
}
__device__ __forceinline__ unsigned long long fma2_3(unsigned long long a,
                                                     unsigned long long b,
                                                     unsigned long long c) {
    unsigned long long d;
    asm("fma.rn.f32x2 %0, %1, %2, %3;" : "=l"(d) : "l"(a), "l"(b), "l"(c));
    return d;
}
__device__ __forceinline__ unsigned long long mul2(unsigned long long a,
                                                   unsigned long long b) {
    unsigned long long d;
    asm("mul.rn.f32x2 %0, %1, %2;" : "=l"(d) : "l"(a), "l"(b));
    return d;
}
__device__ __forceinline__ unsigned long long dup2(float x) {
    unsigned long long r;
    asm("mov.b64 %0, {%1, %1};" : "=l"(r) : "f"(x));
    return r;
}
__device__ __forceinline__ unsigned long long pk2(float x, float y) {
    unsigned long long r;
    asm("mov.b64 %0, {%1, %2};" : "=l"(r) : "f"(x), "f"(y));
    return r;
}
__device__ __forceinline__ float2 unpack2(unsigned long long v) {
    float2 f;
    asm("mov.b64 {%0, %1}, %2;" : "=f"(f.x), "=f"(f.y) : "l"(v));
    return f;
}

// ---------------- RMSNorm (weight folded into GEMM weights) ----------------
__global__ __launch_bounds__(256) void rmsnorm_now(
    const float* __restrict__ X,
    __nv_bfloat16* __restrict__ Yh, __nv_bfloat16* __restrict__ Yl, int rows)
{
    int row  = blockIdx.x * 8 + (threadIdx.x >> 5);
    int lane = threadIdx.x & 31;
    if (row >= rows) return;
    const float* xp = X + (size_t)row * DIM;
    float x[16];
    float ss = 0.f;
#pragma unroll
    for (int t = 0; t < 16; t++) { x[t] = xp[lane + t * 32]; ss += x[t] * x[t]; }
#pragma unroll
    for (int o = 16; o > 0; o >>= 1) ss += __shfl_xor_sync(0xffffffffu, ss, o);
    float rs = rsqrtf(ss * (1.0f / 512.0f) + RMS_EPS);
#pragma unroll
    for (int t = 0; t < 16; t++) {
        int c = lane + t * 32;
        __nv_bfloat16 h, l;
        split_bf16(x[t] * rs, h, l);
        Yh[(size_t)row * DIM + c] = h;
        Yl[(size_t)row * DIM + c] = l;
    }
}

// ---------------- Self attention, split over 4 key-chunks ----------------
__global__ __launch_bounds__(256) void self_attn_part(
    const float* __restrict__ Q, int ldq, const float* __restrict__ KV,
    float* __restrict__ pacc, float* __restrict__ pml, int nbatch)
{
    const int h     = blockIdx.x;
    const int batch = blockIdx.y;
    const int jc    = blockIdx.z;
    const int i     = threadIdx.x;
    const int j0    = jc * 64;

    __shared__ __align__(16) float Ks[64][64];
    __shared__ __align__(16) float Vs[64][64];

    unsigned long long qp[32];
    {
        const float4* qq = reinterpret_cast<const float4*>(
            Q + ((size_t)(batch * 256 + i)) * ldq + h * 64);
#pragma unroll
        for (int t = 0; t < 16; t++) {
            float4 v = qq[t];
            qp[2 * t]     = pk2(v.x, v.y);
            qp[2 * t + 1] = pk2(v.z, v.w);
        }
    }

#pragma unroll
    for (int s = 0; s < 4; s++) {
        int u  = threadIdx.x + s * 256;
        int jr = u >> 4;
        int c4 = u & 15;
        const float* kp = KV + ((size_t)(batch * 256 + j0 + jr)) * 1024 + h * 64 + c4 * 4;
        *reinterpret_cast<float4*>(&Ks[jr][c4 * 4]) = *reinterpret_cast<const float4*>(kp);
        *reinterpret_cast<float4*>(&Vs[jr][c4 * 4]) = *reinterpret_cast<const float4*>(kp + 512);
    }
    __syncthreads();

    float m = -1e30f, l = 0.f;
    unsigned long long acc[32];
#pragma unroll
    for (int t = 0; t < 32; t++) acc[t] = 0ull;

    for (int j = 0; j < 64; j++) {
        const ulonglong2* kr = reinterpret_cast<const ulonglong2*>(Ks[j]);
        unsigned long long s0 = 0ull, s1 = 0ull;
#pragma unroll
        for (int t = 0; t < 8; t++) {
            ulonglong2 k0 = kr[2 * t];
            ulonglong2 k1 = kr[2 * t + 1];
            ffma2(s0, qp[4 * t + 0], k0.x);
            ffma2(s1, qp[4 * t + 1], k0.y);
            ffma2(s0, qp[4 * t + 2], k1.x);
            ffma2(s1, qp[4 * t + 3], k1.y);
        }
        float2 sa = unpack2(s0), sb = unpack2(s1);
        float s = (sa.x + sa.y) + (sb.x + sb.y);

        float mn = fmaxf(m, s);
        float f  = __expf(m - mn);
        float p  = __expf(s - mn);
        l = l * f + p;
        unsigned long long fd = dup2(f), pd = dup2(p);
        const ulonglong2* vr = reinterpret_cast<const ulonglong2*>(Vs[j]);
#pragma unroll
        for (int t = 0; t < 16; t++) {
            ulonglong2 vv = vr[t];
            acc[2 * t]     = fma2_3(acc[2 * t],     fd, mul2(vv.x, pd));
            acc[2 * t + 1] = fma2_3(acc[2 * t + 1], fd, mul2(vv.y, pd));
        }
        m = mn;
    }

    const int bl = (jc * nbatch + batch) * HEADS + h;
    float* pa = pacc + ((size_t)bl * 64) * 256;
#pragma unroll
    for (int t = 0; t < 32; t++) {
        float2 a = unpack2(acc[t]);
        pa[(2 * t) * 256 + i]     = a.x;
        pa[(2 * t + 1) * 256 + i] = a.y;
    }
    pml[(bl * 2 + 0) * 256 + i] = m;
    pml[(bl * 2 + 1) * 256 + i] = l;
}

__global__ __launch_bounds__(256) void self_attn_combine(
    const float* __restrict__ pacc, const float* __restrict__ pml,
    __nv_bfloat16* __restrict__ Oh, __nv_bfloat16* __restrict__ Ol, int nbatch)
{
    int idx   = blockIdx.x * 256 + threadIdx.x;
    int i     = idx & 255;
    int h     = (idx >> 8) & 7;
    int batch = idx >> 11;

    float mc[4], lc[4];
    float M = -1e30f;
#pragma unroll
    for (int c = 0; c < 4; c++) {
        int bl = (c * nbatch + batch) * HEADS + h;
        mc[c] = pml[(bl * 2 + 0) * 256 + i];
        lc[c] = pml[(bl * 2 + 1) * 256 + i];
        M = fmaxf(M, mc[c]);
    }
    float w[4];
    float L = 0.f;
#pragma unroll
    for (int c = 0; c < 4; c++) { w[c] = __expf(mc[c] - M); L += lc[c] * w[c]; }
    float inv = 1.0f / L;

    size_t ob = ((size_t)(batch * 256 + i)) * 512 + h * 64;
#pragma unroll
    for (int t = 0; t < 64; t++) {
        float o = 0.f;
#pragma unroll
        for (int c = 0; c < 4; c++) {
            int bl = (c * nbatch + batch) * HEADS + h;
            o += w[c] * pacc[((size_t)bl * 64 + t) * 256 + i];
        }
        __nv_bfloat16 hh, ll;
        split_bf16(o * inv, hh, ll);
        Oh[ob + t] = hh;
        Ol[ob + t] = ll;
    }
}

// ---------------- Residual attention over unique messages ----------------
__device__ __forceinline__ const float* msg_ptr(
    const float* KVM, int u, int g, int n, float* w)
{
    if (u == 0) { *w = 6.f; return KVM + ((size_t)(g * 256 + n)) * 1024; }
    if (u <= 2) { *w = 6.f;
        return KVM + 524288u + (size_t)(u - 1) * 1048576u + ((size_t)(g * 256 + n)) * 1024; }
    int j = 1 + ((u - 3) >> 2), t = (u - 3) & 3;
    int type = t >> 1, gpp = t & 1;
    *w = 3.f;
    return KVM + 524288u + ((size_t)(j * 2 + type)) * 1048576u
         + ((size_t)((gpp * 2 + g) * 256 + n)) * 1024;
}

__global__ __launch_bounds__(256) void res_attn_kernel(
    const float* __restrict__ Qr, int ldq, int qmask,
    const float* __restrict__ KVM, int Mu,
    __nv_bfloat16* __restrict__ Oh, __nv_bfloat16* __restrict__ Ol)
{
    const int r = blockIdx.x;
    const int g = r >> 9;
    const int n = r & 255;
    const int qrow = r & qmask;

    const int tid  = threadIdx.x;
    const int h    = tid >> 5;
    const int lane = tid & 31;

    __shared__ float qs[512];
    __shared__ float sim[8][16];

    qs[tid]       = Qr[(size_t)qrow * ldq + tid];
    qs[tid + 256] = Qr[(size_t)qrow * ldq + tid + 256];
    __syncthreads();

    float sc = -1e30f;
    float wl = 0.f;
    if (lane < Mu) {
        const float* kpl = msg_ptr(KVM, lane, g, n, &wl);
        const float4* k4 = reinterpret_cast<const float4*>(kpl + h * 64);
        const float4* q4 = reinterpret_cast<const float4*>(&qs[h * 64]);
        float s = 0.f;
#pragma unroll
        for (int t = 0; t < 16; t++) {
            float4 kk = k4[t];
            float4 qq = q4[t];
            s += qq.x * kk.x + qq.y * kk.y + qq.z * kk.z + qq.w * kk.w;
        }
        sc = s;
    }
    float mx = sc;
#pragma unroll
    for (int o = 16; o > 0; o >>= 1) mx = fmaxf(mx, __shfl_xor_sync(0xffffffffu, mx, o));
    float p = (lane < Mu) ? wl * __expf(sc - mx) : 0.f;
    if (lane < 16) sim[h][lane] = p;
    float ls = p;
#pragma unroll
    for (int o = 16; o > 0; o >>= 1) ls += __shfl_xor_sync(0xffffffffu, ls, o);
    __syncwarp();

    float o0 = 0.f, o1 = 0.f;
    for (int u = 0; u < Mu; u++) {
        float a = sim[h][u];
        float dummy;
        const float* vp = msg_ptr(KVM, u, g, n, &dummy) + 512;
        o0 += a * vp[h * 64 + lane];
        o1 += a * vp[h * 64 + lane + 32];
    }
    float inv = 1.0f / ls;
    __nv_bfloat16 hh, ll;
    split_bf16(o0 * inv, hh, ll);
    Oh[(size_t)r * 512 + h * 64 + lane] = hh;
    Ol[(size_t)r * 512 + h * 64 + lane] = ll;
    split_bf16(o1 * inv, hh, ll);
    Oh[(size_t)r * 512 + h * 64 + lane + 32] = hh;
    Ol[(size_t)r * 512 + h * 64 + lane + 32] = ll;
}

// ---------------- GEGLU from g_B (stride NBIG) -> split ACT ----------------
__global__ void geglu_split(const float* __restrict__ B,
                            __nv_bfloat16* __restrict__ Ah,
                            __nv_bfloat16* __restrict__ Al, int count)
{
    int idx = blockIdx.x * blockDim.x + threadIdx.x;
    if (idx >= count) return;
    int row = idx / DFFP;
    int e   = idx - row * DFFP;
    float out = 0.f;
    if (e < DFF) {
        float s = B[(size_t)row * NBIG + 512 + e];
        float gg = B[(size_t)row * NBIG + 512 + DFF + e];
        out = s * (0.5f * gg * (1.0f + erff(gg * 0.70710678118654752440f)));
    }
    __nv_bfloat16 h, l;
    split_bf16(out, h, l);
    Ah[idx] = h;
    Al[idx] = l;
}

// ---------------- init: tokens -> compressed T (dup over g) ----------------
__global__ void init_tok(const float* __restrict__ tokens,
                         float* __restrict__ T,
                         __nv_bfloat16* __restrict__ Th, __nv_bfloat16* __restrict__ Tl)
{
    int idx = blockIdx.x * blockDim.x + threadIdx.x;
    if (idx >= CROWS * DIM) return;
    int d = idx & 511;
    int r = idx >> 9;
    int n = r & 255;
    int b = (r >> 8) & 1;
    float v = tokens[((size_t)(b * 256 + n)) * 512 + d];
    T[idx] = v;
    __nv_bfloat16 h, l;
    split_bf16(v, h, l);
    Th[idx] = h; Tl[idx] = l;
}

// ---------------- fused weight preparation (single launch) ----------------
#define SEG0 1923072               // wbig: NBIG*512
#define SEG1 (SEG0 + 524288)       // wkv
#define SEG2 (SEG1 + 524288)       // rkv
#define SEG3 (SEG2 + 262144)       // rwo
#define SEG4 (SEG3 + 262144)       // woT
#define SEG5 (SEG4 + 720896)       // wvp: 512*1408
#define SEG6 (SEG5 + NBIG)         // bias
__global__ void prep_all(
    const float* __restrict__ wq, const float* __restrict__ ffk,
    const float* __restrict__ rq,
    const float* __restrict__ anw, const float* __restrict__ fnw,
    const float* __restrict__ rnw,
    const float* __restrict__ wkv, const float* __restrict__ rkv,
    const float* __restrict__ rwo, const float* __restrict__ wo,
    const float* __restrict__ wvals, const float* __restrict__ ffb,
    __nv_bfloat16* __restrict__ Wbigh, __nv_bfloat16* __restrict__ Wbigl,
    __nv_bfloat16* __restrict__ Wkvh,  __nv_bfloat16* __restrict__ Wkvl,
    __nv_bfloat16* __restrict__ Rkvh,  __nv_bfloat16* __restrict__ Rkvl,
    __nv_bfloat16* __restrict__ Rwoh,  __nv_bfloat16* __restrict__ Rwol,
    __nv_bfloat16* __restrict__ WoTh,  __nv_bfloat16* __restrict__ WoTl,
    __nv_bfloat16* __restrict__ Wvph,  __nv_bfloat16* __restrict__ Wvpl,
    float* __restrict__ bias)
{
    int idx = blockIdx.x * 256 + threadIdx.x;
    if (idx >= SEG6) return;
    __nv_bfloat16 h, l;
    if (idx < SEG0) {
        int row = idx >> 9, k = idx & 511;
        float v = 0.f;
        if (row < 512)            v = wq [(size_t)row * 512 + k] * anw[k];
        else if (row < QRES_OFF)  v = ffk[(size_t)(row - 512) * 512 + k] * fnw[k];
        else if (row < 3754)      v = rq [(size_t)(row - QRES_OFF) * 512 + k] * rnw[k];
        split_bf16(v, h, l);
        Wbigh[idx] = h; Wbigl[idx] = l;
    } else if (idx < SEG1) {
        int i = idx - SEG0;
        split_bf16(wkv[i], h, l);
        Wkvh[i] = h; Wkvl[i] = l;
    } else if (idx < SEG2) {
        int i = idx - SEG1;
        split_bf16(rkv[i], h, l);
        Rkvh[i] = h; Rkvl[i] = l;
    } else if (idx < SEG3) {
        int i = idx - SEG2;
        split_bf16(rwo[i], h, l);
        Rwoh[i] = h; Rwol[i] = l;
    } else if (idx < SEG4) {
        int i = idx - SEG3;
        int e = i >> 9, d = i & 511;
        split_bf16(wo[(size_t)d * 512 + e], h, l);
        WoTh[i] = h; WoTl[i] = l;
    } else if (idx < SEG5) {
        int i = idx - SEG4;
        int row = i / DFFP, col = i - row * DFFP;
        float v = (col < DFF) ? wvals[(size_t)row * DFF + col] : 0.f;
        split_bf16(v, h, l);
        Wvph[i] = h; Wvpl[i] = l;
    } else {
        int i = idx - SEG5;
        bias[i] = (i >= 512 && i < QRES_OFF) ? ffb[i - 512] : 0.f;
    }
}

// ---------------- expand compressed T -> output (3072 rows) ----------------
__global__ void expand_kernel(const float* __restrict__ T, float* __restrict__ out)
{
    int idx = blockIdx.x * blockDim.x + threadIdx.x;
    if (idx >= 3072 * 512) return;
    int d  = idx & 511;
    int r2 = idx >> 9;
    int n  = r2 & 255;
    int b  = (r2 >> 8) & 1;
    int block = r2 >> 9;
    int g = (2 * block + b) / 6;
    out[idx] = T[((size_t)((g * 2 + b) * 256 + n)) * 512 + d];
}

// -------------------------------- launch --------------------------------------
static float* s_part = nullptr;

static inline void launch_gemm(const __nv_bfloat16* Ah, const __nv_bfloat16* Al, int lda,
                               const __nv_bfloat16* Bh, const __nv_bfloat16* Bl,
                               const float* bias, float* Yf,
                               __nv_bfloat16* Yh, __nv_bfloat16* Yl,
                               int M, int N, int K)
{
    int nx = (N + 63) / 64, my = M / 128;
    int blocks = nx * my;
    int s = (blocks >= 128) ? 1 : ((blocks >= 64) ? 2 : 4);
    dim3 grid(nx, my, s);
    if (s == 1) {
        gemm_mma<<<grid, 256, GSMEM>>>(Ah, Al, lda, Bh, Bl, bias, Yf, Yh, Yl,
                                       M, N, K, 1, nullptr);
    } else {
        gemm_mma<<<grid, 256, GSMEM>>>(Ah, Al, lda, Bh, Bl, nullptr,
                                       nullptr, nullptr, nullptr,
                                       M, N, K, s, s_part);
        int MN = M * N;
        splitk_combine<<<(MN / 2 + 255) / 256, 256>>>(s_part, s, MN, N, bias, Yf, Yh, Yl);
    }
}

extern "C" void kernel_launch(void* const* d_in, const int* in_sizes, int n_in,
                              void* d_out, int out_size)
{
    const float* tokens      = (const float*)d_in[0];
    const float* attn_norm_w = (const float*)d_in[1];
    const float* attn_wq     = (const float*)d_in[2];
    const float* attn_wkv    = (const float*)d_in[3];
    const float* attn_wo     = (const float*)d_in[4];
    const float* ff_norm_w   = (const float*)d_in[5];
    const float* ff_keys_w   = (const float*)d_in[6];
    const float* ff_keys_b   = (const float*)d_in[7];
    const float* ff_values_w = (const float*)d_in[8];
    const float* ff_values_b = (const float*)d_in[9];
    const float* res_norm_w  = (const float*)d_in[10];
    const float* res_wq      = (const float*)d_in[11];
    const float* res_wkv     = (const float*)d_in[12];
    const float* res_wo      = (const float*)d_in[13];
    float* out = (float*)d_out;

    cudaFuncSetAttribute(gemm_mma, cudaFuncAttributeMaxDynamicSharedMemorySize, GSMEM);

    float *B, *T, *KV, *kvm, *bias, *pacc, *pml;
    __nv_bfloat16 *XNh, *XNl, *XAh, *XAl, *ACTh, *ACTl, *RETh, *RETl, *XRh, *XRl, *Th, *Tl;
    __nv_bfloat16 *Wbigh, *Wbigl, *Wkvh, *Wkvl, *Rkvh, *Rkvl, *WoTh, *WoTl;
    __nv_bfloat16 *Wvph, *Wvpl, *Rwoh, *Rwol, *Cath, *Catl;
    cudaGetSymbolAddress((void**)&B,    g_B);
    cudaGetSymbolAddress((void**)&T,    g_T);
    cudaGetSymbolAddress((void**)&KV,   g_KV);
    cudaGetSymbolAddress((void**)&kvm,  g_kvm);
    cudaGetSymbolAddress((void**)&bias, g_bias);
    cudaGetSymbolAddress((void**)&pacc, g_pacc);
    cudaGetSymbolAddress((void**)&pml,  g_pml);
    cudaGetSymbolAddress((void**)&s_part, g_part);
    cudaGetSymbolAddress((void**)&XNh,  g_XNh);  cudaGetSymbolAddress((void**)&XNl, g_XNl);
    cudaGetSymbolAddress((void**)&XAh,  g_XAh);  cudaGetSymbolAddress((void**)&XAl, g_XAl);
    cudaGetSymbolAddress((void**)&ACTh, g_ACTh); cudaGetSymbolAddress((void**)&ACTl, g_ACTl);
    cudaGetSymbolAddress((void**)&RETh, g_RETh); cudaGetSymbolAddress((void**)&RETl, g_RETl);
    cudaGetSymbolAddress((void**)&XRh,  g_XRh);  cudaGetSymbolAddress((void**)&XRl, g_XRl);
    cudaGetSymbolAddress((void**)&Th,   g_Th);   cudaGetSymbolAddress((void**)&Tl,  g_Tl);
    cudaGetSymbolAddress((void**)&Wbigh, g_Wbigh); cudaGetSymbolAddress((void**)&Wbigl, g_Wbigl);
    cudaGetSymbolAddress((void**)&Wkvh, g_Wkvh); cudaGetSymbolAddress((void**)&Wkvl, g_Wkvl);
    cudaGetSymbolAddress((void**)&Rkvh, g_Rkvh); cudaGetSymbolAddress((void**)&Rkvl, g_Rkvl);
    cudaGetSymbolAddress((void**)&WoTh, g_WoTh); cudaGetSymbolAddress((void**)&WoTl, g_WoTl);
    cudaGetSymbolAddress((void**)&Wvph, g_Wvph); cudaGetSymbolAddress((void**)&Wvpl, g_Wvpl);
    cudaGetSymbolAddress((void**)&Rwoh, g_Rwoh); cudaGetSymbolAddress((void**)&Rwol, g_Rwol);
    cudaGetSymbolAddress((void**)&Cath, g_Cath); cudaGetSymbolAddress((void**)&Catl, g_Catl);

    // fused weight prep
    prep_all<<<(SEG6 + 255) / 256, 256>>>(
        attn_wq, ff_keys_w, res_wq, attn_norm_w, ff_norm_w, res_norm_w,
        attn_wkv, res_wkv, res_wo, attn_wo, ff_values_w, ff_keys_b,
        Wbigh, Wbigl, Wkvh, Wkvl, Rkvh, Rkvl, Rwoh, Rwol,
        WoTh, WoTl, Wvph, Wvpl, bias);

    // C_att = res_wkv @ attn_wo
    launch_gemm(Rkvh, Rkvl, 512, WoTh, WoTl, nullptr,
                nullptr, Cath, Catl, 1024, 512, 512);

    // tokens -> compressed T; tokens-kv slab
    init_tok<<<(CROWS * DIM + 255) / 256, 256>>>(tokens, T, Th, Tl);
    launch_gemm(Th, Tl, 512, Rkvh, Rkvl, nullptr,
                kvm, nullptr, nullptr, 512, 1024, 512);

    for (int e = 0; e < 3; e++) {
        const int Mr = (e == 0) ? 512 : 1024;     // e0 is g-degenerate
        const int nb = Mr >> 8;
        float* kv_att = kvm + 524288 + (size_t)(e * 2 + 0) * 1048576;
        float* kv_ret = kvm + 524288 + (size_t)(e * 2 + 1) * 1048576;

        rmsnorm_now<<<Mr / 8, 256>>>(T, XNh, XNl, Mr);
        launch_gemm(XNh, XNl, 512, Wbigh, Wbigl, bias,
                    B, nullptr, nullptr, Mr, NBIG, 512);

        // self-attention (j-split x4 + combine)
        launch_gemm(Th, Tl, 512, Wkvh, Wkvl, nullptr,
                    KV, nullptr, nullptr, Mr, 1024, 512);
        self_attn_part<<<dim3(HEADS, nb, 4), 256>>>(B, NBIG, KV, pacc, pml, nb);
        self_attn_combine<<<nb * 8, 256>>>(pacc, pml, XAh, XAl, nb);

        // attended kv directly (WO folded): kv_att = XA @ C_att^T
        launch_gemm(XAh, XAl, 512, Cath, Catl, nullptr,
                    kv_att, nullptr, nullptr, Mr, 1024, 512);

        // feedforward
        geglu_split<<<(Mr * DFFP + 255) / 256, 256>>>(B, ACTh, ACTl, Mr * DFFP);
        launch_gemm(ACTh, ACTl, DFFP, Wvph, Wvpl, ff_values_b,
                    nullptr, RETh, RETl, Mr, 512, DFFP);
        launch_gemm(RETh, RETl, 512, Rkvh, Rkvl, nullptr,
                    kv_ret, nullptr, nullptr, Mr, 1024, 512);

        // residual pooled attention over unique messages
        res_attn_kernel<<<CROWS, 256>>>(B + QRES_OFF, NBIG, (e == 0) ? 511 : 1023,
                                        kvm, 3 + 4 * e, XRh, XRl);
        launch_gemm(XRh, XRl, 512, Rwoh, Rwol, nullptr,
                    T, (e == 2) ? nullptr : Th, (e == 2) ? nullptr : Tl,
                    CROWS, 512, 512);
    }

    expand_kernel<<<(3072 * 512 + 255) / 256, 256>>>(T, out);
}